// round 3
// baseline (speedup 1.0000x reference)
#include <cuda_runtime.h>
#include <math.h>

#define T_STEPS 512
#define BATCH   64
#define IDIM    256
#define CDIM    512
#define NSLOT   128
#define MDIM    64
#define GATES   2048   // 4*CDIM
#define EPSV    1e-8f
#define NCTA    128

typedef unsigned long long ull;

// ---------------- device scratch (no allocation allowed) ----------------
__device__ float g_pre[(size_t)T_STEPS*BATCH*GATES];  // emb@W_ih_emb^T + b_ih + b_hh
__device__ float g_av [(size_t)T_STEPS*BATCH*MDIM];   // tanh(emb@W_a^T + b_a)
__device__ float g_h  [2][BATCH*CDIM];                // ping-pong h
__device__ float g_r  [BATCH*MDIM];
__device__ unsigned g_bar;

__device__ __forceinline__ float sigmoidf_(float x) { return 1.f/(1.f+expf(-x)); }
__device__ __forceinline__ float softplusf_(float x){ return (x > 20.f) ? x : log1pf(expf(x)); }

// ---- f32x2 helpers (sm_100+) ----
__device__ __forceinline__ ull pk2(float lo, float hi) {
    ull r; asm("mov.b64 %0, {%1, %2};" : "=l"(r) : "f"(lo), "f"(hi)); return r;
}
__device__ __forceinline__ ull pkdup(float x) {
    ull r; asm("mov.b64 %0, {%1, %1};" : "=l"(r) : "f"(x)); return r;
}
__device__ __forceinline__ void upk(ull v, float& lo, float& hi) {
    asm("mov.b64 {%0, %1}, %2;" : "=f"(lo), "=f"(hi) : "l"(v));
}
__device__ __forceinline__ void fma2(ull& acc, ull a, ull b) {
    asm("fma.rn.f32x2 %0, %1, %2, %0;" : "+l"(acc) : "l"(a), "l"(b));
}

// ---------------- state init (runs every replay) ----------------
__global__ void init_state(const float* __restrict__ h0, const float* __restrict__ r0) {
    int stride = gridDim.x * blockDim.x;
    int t0 = blockIdx.x * blockDim.x + threadIdx.x;
    if (t0 == 0) g_bar = 0u;
    for (int i = t0; i < BATCH*CDIM; i += stride)
        g_h[0][i] = h0[i & (CDIM-1)];
    for (int i = t0; i < BATCH*MDIM; i += stride)
        g_r[i] = r0[i & (MDIM-1)];
}

// ---------------- precompute GEMM: g_pre = emb @ W_ih[:, :256]^T + b ----------------
#define GP_TM 128
#define GP_TN 128
#define GP_TK 8
__global__ void __launch_bounds__(256)
gemm_pre(const float* __restrict__ A, const float* __restrict__ W,
         const float* __restrict__ bih, const float* __restrict__ bhh,
         float* __restrict__ C) {
    __shared__ float As[GP_TK][GP_TM+4];
    __shared__ float Bs[GP_TK][GP_TN+4];
    int tid  = threadIdx.x;
    int row0 = blockIdx.y * GP_TM;
    int col0 = blockIdx.x * GP_TN;
    int tx = tid & 15, ty = tid >> 4;

    ull acc2[8][4];
    #pragma unroll
    for (int i = 0; i < 8; i++)
        #pragma unroll
        for (int p = 0; p < 4; p++) acc2[i][p] = 0ull;

    float bv[8];
    #pragma unroll
    for (int j = 0; j < 8; j++) {
        int col = col0 + tx*8 + j;
        bv[j] = bih[col] + bhh[col];
    }

    for (int k0 = 0; k0 < IDIM; k0 += GP_TK) {
        int e  = tid * 4;
        int rr = e >> 3, kk = e & 7;
        float4 va = *(const float4*)&A[(size_t)(row0+rr)*IDIM + k0 + kk];
        As[kk+0][rr] = va.x; As[kk+1][rr] = va.y; As[kk+2][rr] = va.z; As[kk+3][rr] = va.w;
        float4 vb = *(const float4*)&W[(size_t)(col0+rr)*(IDIM+MDIM) + k0 + kk];
        Bs[kk+0][rr] = vb.x; Bs[kk+1][rr] = vb.y; Bs[kk+2][rr] = vb.z; Bs[kk+3][rr] = vb.w;
        __syncthreads();
        #pragma unroll
        for (int kk2 = 0; kk2 < GP_TK; kk2++) {
            float a[8];
            *(float4*)&a[0] = *(const float4*)&As[kk2][ty*8];
            *(float4*)&a[4] = *(const float4*)&As[kk2][ty*8+4];
            ull b2[4];
            const float* bp = &Bs[kk2][tx*8];
            b2[0] = *(const ull*)(bp+0);
            b2[1] = *(const ull*)(bp+2);
            b2[2] = *(const ull*)(bp+4);
            b2[3] = *(const ull*)(bp+6);
            #pragma unroll
            for (int i = 0; i < 8; i++) {
                ull ad = pkdup(a[i]);
                #pragma unroll
                for (int p = 0; p < 4; p++) fma2(acc2[i][p], ad, b2[p]);
            }
        }
        __syncthreads();
    }
    #pragma unroll
    for (int i = 0; i < 8; i++) {
        int row = row0 + ty*8 + i;
        float c[8];
        #pragma unroll
        for (int p = 0; p < 4; p++) upk(acc2[i][p], c[2*p], c[2*p+1]);
        #pragma unroll
        for (int j = 0; j < 8; j += 4) {
            float4 v;
            v.x = c[j+0] + bv[j+0]; v.y = c[j+1] + bv[j+1];
            v.z = c[j+2] + bv[j+2]; v.w = c[j+3] + bv[j+3];
            *(float4*)&C[(size_t)row*GATES + col0 + tx*8 + j] = v;
        }
    }
}

// ---------------- precompute: g_av = tanh(emb @ W_a^T + b_a) ----------------
__global__ void __launch_bounds__(256)
pre_a_kernel(const float* __restrict__ embs, const float* __restrict__ W_a,
             const float* __restrict__ b_a, float* __restrict__ ga) {
    int m  = threadIdx.x & 63;
    int rq = threadIdx.x >> 6;
    int row = blockIdx.x*4 + rq;
    const float* er = embs + (size_t)row*IDIM;
    const float* wr = W_a  + (size_t)m*IDIM;
    float accv = b_a[m];
    #pragma unroll 8
    for (int k = 0; k < IDIM; k += 4) {
        float4 e4 = *(const float4*)&er[k];
        float4 w4 = *(const float4*)&wr[k];
        accv += e4.x*w4.x; accv += e4.y*w4.y;
        accv += e4.z*w4.z; accv += e4.w*w4.w;
    }
    ga[(size_t)row*MDIM + m] = tanhf(accv);
}

// ---------------- software grid barrier ----------------
__device__ __forceinline__ void grid_bar(unsigned target) {
    __syncthreads();
    if (threadIdx.x == 0) {
        __threadfence();
        atomicAdd(&g_bar, 1u);
        while (*(volatile unsigned*)&g_bar < target) { }
    }
    __syncthreads();
}

// ---------------- smem layout for persistent kernel ----------------
#define SW_FLOATS (576*16)           // 9216  : W gate rows [k][jj][gate]
#define SX_FLOATS (576*65)           // 37440 : X [k][b] stride 65
#define SM_FLOATS (NSLOT*MDIM)       // 8192  : persistent Mem (CTAs < 64)
#define SMEM_TOT_BYTES ((SW_FLOATS + SX_FLOATS + SM_FLOATS) * 4)

// ---------------- phase B: per-batch NTM memory ops ----------------
__device__ void phase_mem(int bb, int tid, float* sh_mem, float* sb,
                          const float* __restrict__ hc,
                          const float* __restrict__ W_kr, const float* __restrict__ b_kr,
                          const float* __restrict__ w_br,
                          const float* __restrict__ W_kw, const float* __restrict__ b_kw,
                          const float* __restrict__ w_bw,
                          const float* __restrict__ W_e,  const float* __restrict__ b_e,
                          const float* __restrict__ av_t,
                          float* __restrict__ r_out, float* __restrict__ out_t) {
    float* sh_co  = sb;
    float* sh_kw  = sb + 512;
    float* sh_kr  = sb + 576;
    float* sh_e   = sb + 640;
    float* sh_a   = sb + 704;
    float* sh_wt  = sb + 768;
    float* sh_sim = sb + 896;
    float* sh_nrm = sb + 1024;
    float* sh_red = sb + 1152;   // 768
    float* sh_scal= sb + 1920;   // 8
    int lane = tid & 31, warp = tid >> 5;

    for (int i = tid; i < CDIM; i += 256) sh_co[i] = __ldcg(&hc[bb*CDIM + i]);
    if (tid < MDIM) sh_a[tid] = av_t[bb*MDIM + tid];
    __syncthreads();

    // projections kw, kr, e (K split across 4 groups)
    {
        int m = tid & 63, p = tid >> 6;
        int k0 = p*128;
        const float* wkw = W_kw + (size_t)m*CDIM + k0;
        const float* wkr = W_kr + (size_t)m*CDIM + k0;
        const float* we  = W_e  + (size_t)m*CDIM + k0;
        float aw = 0.f, ar = 0.f, ae = 0.f;
        #pragma unroll 4
        for (int k = 0; k < 128; k += 4) {
            float4 cv = *(const float4*)&sh_co[k0+k];
            float4 u  = *(const float4*)&wkw[k];
            aw += cv.x*u.x; aw += cv.y*u.y; aw += cv.z*u.z; aw += cv.w*u.w;
            float4 v  = *(const float4*)&wkr[k];
            ar += cv.x*v.x; ar += cv.y*v.y; ar += cv.z*v.z; ar += cv.w*v.w;
            float4 w  = *(const float4*)&we[k];
            ae += cv.x*w.x; ae += cv.y*w.y; ae += cv.z*w.z; ae += cv.w*w.w;
        }
        sh_red[0*256 + m*4 + p] = aw;
        sh_red[1*256 + m*4 + p] = ar;
        sh_red[2*256 + m*4 + p] = ae;
    }
    __syncthreads();
    if (tid < MDIM) {
        int m = tid;
        float sw = sh_red[m*4] + sh_red[m*4+1] + sh_red[m*4+2] + sh_red[m*4+3];
        float sr = sh_red[256+m*4] + sh_red[256+m*4+1] + sh_red[256+m*4+2] + sh_red[256+m*4+3];
        float se = sh_red[512+m*4] + sh_red[512+m*4+1] + sh_red[512+m*4+2] + sh_red[512+m*4+3];
        sh_kw[m] = tanhf(sw + b_kw[m]);
        sh_kr[m] = tanhf(sr + b_kr[m]);
        sh_e[m]  = sigmoidf_(se + b_e[m]);
    }
    if (warp == 2) {
        float acc = 0.f;
        for (int k = lane; k < CDIM; k += 32) acc += sh_co[k]*w_bw[k];
        #pragma unroll
        for (int off = 16; off > 0; off >>= 1) acc += __shfl_down_sync(0xffffffffu, acc, off);
        if (lane == 0) sh_scal[0] = softplusf_(acc);
    }
    if (warp == 3) {
        float acc = 0.f;
        for (int k = lane; k < CDIM; k += 32) acc += sh_co[k]*w_br[k];
        #pragma unroll
        for (int off = 16; off > 0; off >>= 1) acc += __shfl_down_sync(0xffffffffu, acc, off);
        if (lane == 0) sh_scal[1] = softplusf_(acc);
    }
    __syncthreads();

    // ---- WRITE addressing ----
    for (int n = warp; n < NSLOT; n += 8) {
        const float* Mn = &sh_mem[n*MDIM];
        float m1 = Mn[lane], m2 = Mn[lane+32];
        float s = m1*sh_kw[lane] + m2*sh_kw[lane+32];
        float q = m1*m1 + m2*m2;
        #pragma unroll
        for (int off = 16; off > 0; off >>= 1) {
            s += __shfl_down_sync(0xffffffffu, s, off);
            q += __shfl_down_sync(0xffffffffu, q, off);
        }
        if (lane == 0) { sh_sim[n] = s; sh_nrm[n] = sqrtf(q); }
    }
    if (warp == 0) {
        float kv1 = sh_kw[lane], kv2 = sh_kw[lane+32];
        float q = kv1*kv1 + kv2*kv2;
        #pragma unroll
        for (int off = 16; off > 0; off >>= 1) q += __shfl_down_sync(0xffffffffu, q, off);
        if (lane == 0) sh_scal[2] = sqrtf(q);
    }
    __syncthreads();
    if (tid < NSLOT)
        sh_wt[tid] = sh_scal[0] * (sh_sim[tid] / (sh_nrm[tid]*sh_scal[2] + EPSV));
    __syncthreads();
    if (tid < 32) {
        float v0 = sh_wt[lane], v1 = sh_wt[lane+32], v2 = sh_wt[lane+64], v3 = sh_wt[lane+96];
        float mx = fmaxf(fmaxf(v0,v1), fmaxf(v2,v3));
        #pragma unroll
        for (int off = 16; off > 0; off >>= 1) mx = fmaxf(mx, __shfl_xor_sync(0xffffffffu, mx, off));
        float e0 = expf(v0-mx), e1 = expf(v1-mx), e2 = expf(v2-mx), e3 = expf(v3-mx);
        float ss = e0+e1+e2+e3;
        #pragma unroll
        for (int off = 16; off > 0; off >>= 1) ss += __shfl_xor_sync(0xffffffffu, ss, off);
        float inv = 1.f/ss;
        sh_wt[lane] = e0*inv; sh_wt[lane+32] = e1*inv; sh_wt[lane+64] = e2*inv; sh_wt[lane+96] = e3*inv;
    }
    __syncthreads();

    // ---- memory update (smem only) ----
    for (int i = tid; i < NSLOT*MDIM/4; i += 256) {
        int n = i >> 4, m4 = (i & 15)*4;
        float wn = sh_wt[n];
        float4 mm = *(float4*)&sh_mem[n*MDIM + m4];
        float4 ee = *(const float4*)&sh_e[m4];
        float4 aa = *(const float4*)&sh_a[m4];
        mm.x = mm.x*(1.f - wn*ee.x) + wn*aa.x;
        mm.y = mm.y*(1.f - wn*ee.y) + wn*aa.y;
        mm.z = mm.z*(1.f - wn*ee.z) + wn*aa.z;
        mm.w = mm.w*(1.f - wn*ee.w) + wn*aa.w;
        *(float4*)&sh_mem[n*MDIM + m4] = mm;
    }
    __syncthreads();

    // ---- READ addressing ----
    for (int n = warp; n < NSLOT; n += 8) {
        const float* Mn = &sh_mem[n*MDIM];
        float m1 = Mn[lane], m2 = Mn[lane+32];
        float s = m1*sh_kr[lane] + m2*sh_kr[lane+32];
        float q = m1*m1 + m2*m2;
        #pragma unroll
        for (int off = 16; off > 0; off >>= 1) {
            s += __shfl_down_sync(0xffffffffu, s, off);
            q += __shfl_down_sync(0xffffffffu, q, off);
        }
        if (lane == 0) { sh_sim[n] = s; sh_nrm[n] = sqrtf(q); }
    }
    if (warp == 0) {
        float kv1 = sh_kr[lane], kv2 = sh_kr[lane+32];
        float q = kv1*kv1 + kv2*kv2;
        #pragma unroll
        for (int off = 16; off > 0; off >>= 1) q += __shfl_down_sync(0xffffffffu, q, off);
        if (lane == 0) sh_scal[3] = sqrtf(q);
    }
    __syncthreads();
    if (tid < NSLOT)
        sh_wt[tid] = sh_scal[1] * (sh_sim[tid] / (sh_nrm[tid]*sh_scal[3] + EPSV));
    __syncthreads();
    if (tid < 32) {
        float v0 = sh_wt[lane], v1 = sh_wt[lane+32], v2 = sh_wt[lane+64], v3 = sh_wt[lane+96];
        float mx = fmaxf(fmaxf(v0,v1), fmaxf(v2,v3));
        #pragma unroll
        for (int off = 16; off > 0; off >>= 1) mx = fmaxf(mx, __shfl_xor_sync(0xffffffffu, mx, off));
        float e0 = expf(v0-mx), e1 = expf(v1-mx), e2 = expf(v2-mx), e3 = expf(v3-mx);
        float ss = e0+e1+e2+e3;
        #pragma unroll
        for (int off = 16; off > 0; off >>= 1) ss += __shfl_xor_sync(0xffffffffu, ss, off);
        float inv = 1.f/ss;
        sh_wt[lane] = e0*inv; sh_wt[lane+32] = e1*inv; sh_wt[lane+64] = e2*inv; sh_wt[lane+96] = e3*inv;
    }
    __syncthreads();

    // ---- r = wr @ Mem ----
    {
        int m = tid & 63, p = tid >> 6;
        float acc = 0.f;
        int n0 = p*32;
        #pragma unroll 8
        for (int n = n0; n < n0+32; n++)
            acc += sh_wt[n] * sh_mem[n*MDIM + m];
        sh_red[m*4 + p] = acc;
    }
    __syncthreads();
    if (tid < MDIM) {
        float rv = sh_red[tid*4] + sh_red[tid*4+1] + sh_red[tid*4+2] + sh_red[tid*4+3];
        r_out[bb*MDIM + tid] = rv;
        out_t[bb*576 + 512 + tid] = rv;
    }
    __syncthreads();
}

// ---------------- persistent recurrence kernel ----------------
__global__ void __launch_bounds__(256, 1)
persist(const float* __restrict__ W_ih, const float* __restrict__ W_hh,
        const float* __restrict__ c0,   const float* __restrict__ mem0,
        const float* __restrict__ W_kr, const float* __restrict__ b_kr, const float* __restrict__ w_br,
        const float* __restrict__ W_kw, const float* __restrict__ b_kw, const float* __restrict__ w_bw,
        const float* __restrict__ W_e,  const float* __restrict__ b_e,
        float* __restrict__ out) {
    extern __shared__ float sm[];
    float* sh_w   = sm;                        // [576][16] : [k][jj][gate]
    float* sh_x   = sm + SW_FLOATS;            // [576][65] : [k][b] pad 65
    float* sh_mem = sm + SW_FLOATS + SX_FLOATS;
    float* sb     = sh_x;                      // phase-B scratch aliases sh_x

    int cta = blockIdx.x;
    int tid = threadIdx.x;
    int b   = tid & 63;
    int jj  = tid >> 6;
    int j   = cta*4 + jj;

    // one-time: stage 16 gate weight rows [k=0..575][jj][gate]
    for (int i = tid; i < SW_FLOATS; i += 256) {
        int k = i >> 4, jjj = (i >> 2) & 3, g = i & 3;
        int row = g*CDIM + cta*4 + jjj;
        float v = (k < CDIM) ? W_hh[(size_t)row*CDIM + k]
                             : W_ih[(size_t)row*(IDIM+MDIM) + IDIM + (k - CDIM)];
        sh_w[i] = v;
    }
    if (cta < BATCH)
        for (int i = tid; i < SM_FLOATS; i += 256) sh_mem[i] = mem0[i];
    float creg = c0[j];
    __syncthreads();

    unsigned target = 0;
    for (int t = 0; t < T_STEPS; t++) {
        int hsel = t & 1, hcur = hsel ^ 1;
        const float* hp = g_h[hsel];

        // stage X = [h | r] transposed to [k][b] (stride 65)
        for (int i = tid; i < 8192; i += 256) {
            int bb = i >> 7, k4 = (i & 127)*4;
            float4 v = __ldcg((const float4*)&hp[bb*CDIM + k4]);
            sh_x[(k4+0)*65 + bb] = v.x;
            sh_x[(k4+1)*65 + bb] = v.y;
            sh_x[(k4+2)*65 + bb] = v.z;
            sh_x[(k4+3)*65 + bb] = v.w;
        }
        for (int i = tid; i < 1024; i += 256) {
            int bb = i >> 4, m4 = (i & 15)*4;
            float4 v = __ldcg((const float4*)&g_r[bb*MDIM + m4]);
            sh_x[(512+m4+0)*65 + bb] = v.x;
            sh_x[(512+m4+1)*65 + bb] = v.y;
            sh_x[(512+m4+2)*65 + bb] = v.z;
            sh_x[(512+m4+3)*65 + bb] = v.w;
        }
        __syncthreads();

        // gates: acc01 = {i,f}, acc23 = {g,o}
        const float* pre = g_pre + ((size_t)t*BATCH + b)*GATES + j;
        ull acc01 = pk2(pre[0],    pre[512]);
        ull acc23 = pk2(pre[1024], pre[1536]);
        const float* wp = sh_w + jj*4;
        #pragma unroll 8
        for (int k = 0; k < 576; k++) {
            ull xd  = pkdup(sh_x[k*65 + b]);
            ull w01 = *(const ull*)(wp + k*16);
            ull w23 = *(const ull*)(wp + k*16 + 2);
            fma2(acc01, w01, xd);
            fma2(acc23, w23, xd);
        }
        float ai, af, ag, ao;
        upk(acc01, ai, af);
        upk(acc23, ag, ao);
        float iv = sigmoidf_(ai), fv = sigmoidf_(af), ov = sigmoidf_(ao);
        float gv = tanhf(ag);
        creg = fv*creg + iv*gv;
        float hn = ov * tanhf(creg);
        g_h[hcur][b*CDIM + j] = hn;
        float* out_t = out + (size_t)t*BATCH*(CDIM+MDIM);
        out_t[b*576 + j] = hn;

        target += NCTA; grid_bar(target);

        if (cta < BATCH) {
            phase_mem(cta, tid, sh_mem, sb, g_h[hcur],
                      W_kr, b_kr, w_br, W_kw, b_kw, w_bw, W_e, b_e,
                      g_av + (size_t)t*BATCH*MDIM, g_r, out_t);
        }

        target += NCTA; grid_bar(target);
    }
}

// ---------------- launch ----------------
extern "C" void kernel_launch(void* const* d_in, const int* in_sizes, int n_in,
                              void* d_out, int out_size) {
    const float* embs = (const float*)d_in[0];
    const float* W_ih = (const float*)d_in[1];
    const float* W_hh = (const float*)d_in[2];
    const float* b_ih = (const float*)d_in[3];
    const float* b_hh = (const float*)d_in[4];
    const float* W_kr = (const float*)d_in[5];
    const float* b_kr = (const float*)d_in[6];
    const float* w_br = (const float*)d_in[7];
    const float* W_kw = (const float*)d_in[8];
    const float* b_kw = (const float*)d_in[9];
    const float* w_bw = (const float*)d_in[10];
    const float* W_e  = (const float*)d_in[11];
    const float* b_e  = (const float*)d_in[12];
    const float* W_a  = (const float*)d_in[13];
    const float* b_a  = (const float*)d_in[14];
    const float* h0   = (const float*)d_in[15];
    const float* c0   = (const float*)d_in[16];
    const float* r0   = (const float*)d_in[17];
    const float* mem0 = (const float*)d_in[18];
    float* out = (float*)d_out;

    float *p_pre, *p_av;
    cudaGetSymbolAddress((void**)&p_pre, g_pre);
    cudaGetSymbolAddress((void**)&p_av,  g_av);

    cudaFuncSetAttribute(persist, cudaFuncAttributeMaxDynamicSharedMemorySize, SMEM_TOT_BYTES);

    init_state<<<128, 256>>>(h0, r0);
    gemm_pre<<<dim3(GATES/GP_TN, (T_STEPS*BATCH)/GP_TM), 256>>>(embs, W_ih, b_ih, b_hh, p_pre);
    pre_a_kernel<<<(T_STEPS*BATCH)/4, 256>>>(embs, W_a, b_a, p_av);
    persist<<<NCTA, 256, SMEM_TOT_BYTES>>>(W_ih, W_hh, c0, mem0,
                                           W_kr, b_kr, w_br, W_kw, b_kw, w_bw,
                                           W_e, b_e, out);
}

// round 4
// speedup vs baseline: 1.4652x; 1.4652x over previous
#include <cuda_runtime.h>
#include <math.h>

#define T_STEPS 512
#define BATCH   64
#define IDIM    256
#define CDIM    512
#define NSLOT   128
#define MDIM    64
#define GATES   2048
#define EPSV    1e-8f
#define NCTA    128

typedef unsigned long long ull;

// ---------------- device scratch ----------------
__device__ float g_pre[(size_t)T_STEPS*BATCH*GATES];
__device__ float g_av [(size_t)T_STEPS*BATCH*MDIM];
__device__ float g_WT [3][CDIM*MDIM];                // transposed W_kw, W_kr, W_e : [k][m]
__device__ float g_h  [2][BATCH*CDIM];
__device__ float g_r  [BATCH*MDIM];
__device__ unsigned g_bar;

__device__ __forceinline__ float sigmoidf_(float x) { return 1.f/(1.f+expf(-x)); }
__device__ __forceinline__ float softplusf_(float x){ return (x > 20.f) ? x : log1pf(expf(x)); }

// ---- f32x2 helpers ----
__device__ __forceinline__ void upk(ull v, float& lo, float& hi) {
    asm("mov.b64 {%0, %1}, %2;" : "=f"(lo), "=f"(hi) : "l"(v));
}
__device__ __forceinline__ void fma2(ull& acc, ull a, ull b) {
    asm("fma.rn.f32x2 %0, %1, %2, %0;" : "+l"(acc) : "l"(a), "l"(b));
}
__device__ __forceinline__ unsigned cvta_sm(const void* p) {
    return (unsigned)__cvta_generic_to_shared(p);
}
#define LDS2(lo, hi, addr, OFF) \
  asm volatile("ld.shared.v2.u64 {%0,%1}, [%2+" #OFF "];" : "=l"(lo), "=l"(hi) : "r"(addr))

// ---------------- state init ----------------
__global__ void init_state(const float* __restrict__ h0, const float* __restrict__ r0) {
    int stride = gridDim.x * blockDim.x;
    int t0 = blockIdx.x * blockDim.x + threadIdx.x;
    if (t0 == 0) g_bar = 0u;
    for (int i = t0; i < BATCH*CDIM; i += stride)
        g_h[0][i] = h0[i & (CDIM-1)];
    for (int i = t0; i < BATCH*MDIM; i += stride)
        g_r[i] = r0[i & (MDIM-1)];
}

// ---------------- transpose projection weights : WT[k*64+m] = W[m*512+k] ----------------
__global__ void __launch_bounds__(256)
transpose_w(const float* __restrict__ Wkw, const float* __restrict__ Wkr,
            const float* __restrict__ We) {
    int idx = blockIdx.x*256 + threadIdx.x;   // 0..32767
    int k = idx >> 6, m = idx & 63;
    g_WT[0][idx] = Wkw[m*CDIM + k];
    g_WT[1][idx] = Wkr[m*CDIM + k];
    g_WT[2][idx] = We [m*CDIM + k];
}

// ---------------- precompute GEMM: g_pre = emb @ W_ih[:, :256]^T + b ----------------
#define GP_TM 128
#define GP_TN 128
#define GP_TK 8
__global__ void __launch_bounds__(256)
gemm_pre(const float* __restrict__ A, const float* __restrict__ W,
         const float* __restrict__ bih, const float* __restrict__ bhh,
         float* __restrict__ C) {
    __shared__ float As[GP_TK][GP_TM+4];
    __shared__ float Bs[GP_TK][GP_TN+4];
    int tid  = threadIdx.x;
    int row0 = blockIdx.y * GP_TM;
    int col0 = blockIdx.x * GP_TN;
    int tx = tid & 15, ty = tid >> 4;

    ull acc2[8][4];
    #pragma unroll
    for (int i = 0; i < 8; i++)
        #pragma unroll
        for (int p = 0; p < 4; p++) acc2[i][p] = 0ull;

    float bv[8];
    #pragma unroll
    for (int j = 0; j < 8; j++) {
        int col = col0 + tx*8 + j;
        bv[j] = bih[col] + bhh[col];
    }

    for (int k0 = 0; k0 < IDIM; k0 += GP_TK) {
        int e  = tid * 4;
        int rr = e >> 3, kk = e & 7;
        float4 va = *(const float4*)&A[(size_t)(row0+rr)*IDIM + k0 + kk];
        As[kk+0][rr] = va.x; As[kk+1][rr] = va.y; As[kk+2][rr] = va.z; As[kk+3][rr] = va.w;
        float4 vb = *(const float4*)&W[(size_t)(col0+rr)*(IDIM+MDIM) + k0 + kk];
        Bs[kk+0][rr] = vb.x; Bs[kk+1][rr] = vb.y; Bs[kk+2][rr] = vb.z; Bs[kk+3][rr] = vb.w;
        __syncthreads();
        #pragma unroll
        for (int kk2 = 0; kk2 < GP_TK; kk2++) {
            float a[8];
            *(float4*)&a[0] = *(const float4*)&As[kk2][ty*8];
            *(float4*)&a[4] = *(const float4*)&As[kk2][ty*8+4];
            ull b2[4];
            const float* bp = &Bs[kk2][tx*8];
            b2[0] = *(const ull*)(bp+0);
            b2[1] = *(const ull*)(bp+2);
            b2[2] = *(const ull*)(bp+4);
            b2[3] = *(const ull*)(bp+6);
            #pragma unroll
            for (int i = 0; i < 8; i++) {
                ull ad; asm("mov.b64 %0, {%1, %1};" : "=l"(ad) : "f"(a[i]));
                #pragma unroll
                for (int p = 0; p < 4; p++) fma2(acc2[i][p], ad, b2[p]);
            }
        }
        __syncthreads();
    }
    #pragma unroll
    for (int i = 0; i < 8; i++) {
        int row = row0 + ty*8 + i;
        float c[8];
        #pragma unroll
        for (int p = 0; p < 4; p++) upk(acc2[i][p], c[2*p], c[2*p+1]);
        #pragma unroll
        for (int j = 0; j < 8; j += 4) {
            float4 v;
            v.x = c[j+0] + bv[j+0]; v.y = c[j+1] + bv[j+1];
            v.z = c[j+2] + bv[j+2]; v.w = c[j+3] + bv[j+3];
            *(float4*)&C[(size_t)row*GATES + col0 + tx*8 + j] = v;
        }
    }
}

// ---------------- precompute: g_av = tanh(emb @ W_a^T + b_a) ----------------
__global__ void __launch_bounds__(256)
pre_a_kernel(const float* __restrict__ embs, const float* __restrict__ W_a,
             const float* __restrict__ b_a, float* __restrict__ ga) {
    int m  = threadIdx.x & 63;
    int rq = threadIdx.x >> 6;
    int row = blockIdx.x*4 + rq;
    const float* er = embs + (size_t)row*IDIM;
    const float* wr = W_a  + (size_t)m*IDIM;
    float accv = b_a[m];
    #pragma unroll 8
    for (int k = 0; k < IDIM; k += 4) {
        float4 e4 = *(const float4*)&er[k];
        float4 w4 = *(const float4*)&wr[k];
        accv += e4.x*w4.x; accv += e4.y*w4.y;
        accv += e4.z*w4.z; accv += e4.w*w4.w;
    }
    ga[(size_t)row*MDIM + m] = tanhf(accv);
}

// ---------------- software grid barrier ----------------
__device__ __forceinline__ void grid_bar(unsigned target) {
    __syncthreads();
    if (threadIdx.x == 0) {
        __threadfence();
        atomicAdd(&g_bar, 1u);
        while (*(volatile unsigned*)&g_bar < target) { }
    }
    __syncthreads();
}

// ---------------- smem layout ----------------
#define SW_FLOATS   (4*4*576)     // 9216  : [j_local][gate][k]
#define SX_STRIDE   580
#define SX_FLOATS   (64*SX_STRIDE) // 37120 : x [b][k] pad 580
#define SM_FLOATS   (NSLOT*MDIM)  // 8192
#define SPRE_FLOATS (4*4*64)      // 1024  : [gate][j_local][b]
#define SRED2_FLOATS (128*9)      // 1152
#define SMEM_TOT_BYTES ((SW_FLOATS + SX_FLOATS + SM_FLOATS + SPRE_FLOATS + SRED2_FLOATS) * 4)

// ---------------- phase B: per-batch NTM memory ops (256 threads) ----------------
__device__ void phase_mem(int bb, int tid, float* sh_mem, float* sb,
                          const float* __restrict__ hc,
                          const float* __restrict__ b_kr, const float* __restrict__ w_br,
                          const float* __restrict__ b_kw, const float* __restrict__ w_bw,
                          const float* __restrict__ b_e,
                          const float* __restrict__ av_t,
                          float* __restrict__ r_out, float* __restrict__ out_t) {
    float* sh_co  = sb;
    float* sh_kw  = sb + 512;
    float* sh_kr  = sb + 576;
    float* sh_e   = sb + 640;
    float* sh_a   = sb + 704;
    float* sh_wt  = sb + 768;
    float* sh_sim = sb + 896;
    float* sh_nrm = sb + 1024;
    float* sh_red = sb + 1152;   // 768
    float* sh_scal= sb + 1920;   // 8
    int lane = tid & 31, warp = tid >> 5;

    for (int i = tid; i < CDIM; i += 256) sh_co[i] = __ldcg(&hc[bb*CDIM + i]);
    if (tid < MDIM) sh_a[tid] = av_t[bb*MDIM + tid];
    __syncthreads();

    // projections from TRANSPOSED weights (coalesced)
    {
        int m = tid & 63, p = tid >> 6;
        int k0 = p*128;
        const float* WTw = g_WT[0];
        const float* WTr = g_WT[1];
        const float* WTe = g_WT[2];
        float aw = 0.f, ar = 0.f, ae = 0.f;
        #pragma unroll 4
        for (int k = k0; k < k0+128; k++) {
            float c = sh_co[k];
            aw = fmaf(c, __ldg(&WTw[k*64+m]), aw);
            ar = fmaf(c, __ldg(&WTr[k*64+m]), ar);
            ae = fmaf(c, __ldg(&WTe[k*64+m]), ae);
        }
        sh_red[0*256 + m*4 + p] = aw;
        sh_red[1*256 + m*4 + p] = ar;
        sh_red[2*256 + m*4 + p] = ae;
    }
    __syncthreads();
    if (tid < MDIM) {
        int m = tid;
        float sw = sh_red[m*4] + sh_red[m*4+1] + sh_red[m*4+2] + sh_red[m*4+3];
        float sr = sh_red[256+m*4] + sh_red[256+m*4+1] + sh_red[256+m*4+2] + sh_red[256+m*4+3];
        float se = sh_red[512+m*4] + sh_red[512+m*4+1] + sh_red[512+m*4+2] + sh_red[512+m*4+3];
        sh_kw[m] = tanhf(sw + b_kw[m]);
        sh_kr[m] = tanhf(sr + b_kr[m]);
        sh_e[m]  = sigmoidf_(se + b_e[m]);
    }
    if (warp == 2) {
        float acc = 0.f;
        for (int k = lane; k < CDIM; k += 32) acc += sh_co[k]*w_bw[k];
        #pragma unroll
        for (int off = 16; off > 0; off >>= 1) acc += __shfl_down_sync(0xffffffffu, acc, off);
        if (lane == 0) sh_scal[0] = softplusf_(acc);
    }
    if (warp == 3) {
        float acc = 0.f;
        for (int k = lane; k < CDIM; k += 32) acc += sh_co[k]*w_br[k];
        #pragma unroll
        for (int off = 16; off > 0; off >>= 1) acc += __shfl_down_sync(0xffffffffu, acc, off);
        if (lane == 0) sh_scal[1] = softplusf_(acc);
    }
    __syncthreads();

    // ---- WRITE addressing ----
    for (int n = warp; n < NSLOT; n += 8) {
        const float* Mn = &sh_mem[n*MDIM];
        float m1 = Mn[lane], m2 = Mn[lane+32];
        float s = m1*sh_kw[lane] + m2*sh_kw[lane+32];
        float q = m1*m1 + m2*m2;
        #pragma unroll
        for (int off = 16; off > 0; off >>= 1) {
            s += __shfl_down_sync(0xffffffffu, s, off);
            q += __shfl_down_sync(0xffffffffu, q, off);
        }
        if (lane == 0) { sh_sim[n] = s; sh_nrm[n] = sqrtf(q); }
    }
    if (warp == 0) {
        float kv1 = sh_kw[lane], kv2 = sh_kw[lane+32];
        float q = kv1*kv1 + kv2*kv2;
        #pragma unroll
        for (int off = 16; off > 0; off >>= 1) q += __shfl_down_sync(0xffffffffu, q, off);
        if (lane == 0) sh_scal[2] = sqrtf(q);
    }
    __syncthreads();
    if (tid < NSLOT)
        sh_wt[tid] = sh_scal[0] * (sh_sim[tid] / (sh_nrm[tid]*sh_scal[2] + EPSV));
    __syncthreads();
    if (tid < 32) {
        float v0 = sh_wt[lane], v1 = sh_wt[lane+32], v2 = sh_wt[lane+64], v3 = sh_wt[lane+96];
        float mx = fmaxf(fmaxf(v0,v1), fmaxf(v2,v3));
        #pragma unroll
        for (int off = 16; off > 0; off >>= 1) mx = fmaxf(mx, __shfl_xor_sync(0xffffffffu, mx, off));
        float e0 = expf(v0-mx), e1 = expf(v1-mx), e2 = expf(v2-mx), e3 = expf(v3-mx);
        float ss = e0+e1+e2+e3;
        #pragma unroll
        for (int off = 16; off > 0; off >>= 1) ss += __shfl_xor_sync(0xffffffffu, ss, off);
        float inv = 1.f/ss;
        sh_wt[lane] = e0*inv; sh_wt[lane+32] = e1*inv; sh_wt[lane+64] = e2*inv; sh_wt[lane+96] = e3*inv;
    }
    __syncthreads();

    // ---- memory update (smem only) ----
    for (int i = tid; i < NSLOT*MDIM/4; i += 256) {
        int n = i >> 4, m4 = (i & 15)*4;
        float wn = sh_wt[n];
        float4 mm = *(float4*)&sh_mem[n*MDIM + m4];
        float4 ee = *(const float4*)&sh_e[m4];
        float4 aa = *(const float4*)&sh_a[m4];
        mm.x = mm.x*(1.f - wn*ee.x) + wn*aa.x;
        mm.y = mm.y*(1.f - wn*ee.y) + wn*aa.y;
        mm.z = mm.z*(1.f - wn*ee.z) + wn*aa.z;
        mm.w = mm.w*(1.f - wn*ee.w) + wn*aa.w;
        *(float4*)&sh_mem[n*MDIM + m4] = mm;
    }
    __syncthreads();

    // ---- READ addressing ----
    for (int n = warp; n < NSLOT; n += 8) {
        const float* Mn = &sh_mem[n*MDIM];
        float m1 = Mn[lane], m2 = Mn[lane+32];
        float s = m1*sh_kr[lane] + m2*sh_kr[lane+32];
        float q = m1*m1 + m2*m2;
        #pragma unroll
        for (int off = 16; off > 0; off >>= 1) {
            s += __shfl_down_sync(0xffffffffu, s, off);
            q += __shfl_down_sync(0xffffffffu, q, off);
        }
        if (lane == 0) { sh_sim[n] = s; sh_nrm[n] = sqrtf(q); }
    }
    if (warp == 0) {
        float kv1 = sh_kr[lane], kv2 = sh_kr[lane+32];
        float q = kv1*kv1 + kv2*kv2;
        #pragma unroll
        for (int off = 16; off > 0; off >>= 1) q += __shfl_down_sync(0xffffffffu, q, off);
        if (lane == 0) sh_scal[3] = sqrtf(q);
    }
    __syncthreads();
    if (tid < NSLOT)
        sh_wt[tid] = sh_scal[1] * (sh_sim[tid] / (sh_nrm[tid]*sh_scal[3] + EPSV));
    __syncthreads();
    if (tid < 32) {
        float v0 = sh_wt[lane], v1 = sh_wt[lane+32], v2 = sh_wt[lane+64], v3 = sh_wt[lane+96];
        float mx = fmaxf(fmaxf(v0,v1), fmaxf(v2,v3));
        #pragma unroll
        for (int off = 16; off > 0; off >>= 1) mx = fmaxf(mx, __shfl_xor_sync(0xffffffffu, mx, off));
        float e0 = expf(v0-mx), e1 = expf(v1-mx), e2 = expf(v2-mx), e3 = expf(v3-mx);
        float ss = e0+e1+e2+e3;
        #pragma unroll
        for (int off = 16; off > 0; off >>= 1) ss += __shfl_xor_sync(0xffffffffu, ss, off);
        float inv = 1.f/ss;
        sh_wt[lane] = e0*inv; sh_wt[lane+32] = e1*inv; sh_wt[lane+64] = e2*inv; sh_wt[lane+96] = e3*inv;
    }
    __syncthreads();

    // ---- r = wr @ Mem ----
    {
        int m = tid & 63, p = tid >> 6;
        float acc = 0.f;
        int n0 = p*32;
        #pragma unroll 8
        for (int n = n0; n < n0+32; n++)
            acc += sh_wt[n] * sh_mem[n*MDIM + m];
        sh_red[m*4 + p] = acc;
    }
    __syncthreads();
    if (tid < MDIM) {
        float rv = sh_red[tid*4] + sh_red[tid*4+1] + sh_red[tid*4+2] + sh_red[tid*4+3];
        r_out[bb*MDIM + tid] = rv;
        out_t[bb*576 + 512 + tid] = rv;
    }
    __syncthreads();
}

// ---------------- persistent recurrence kernel ----------------
__global__ void __launch_bounds__(256, 1)
persist(const float* __restrict__ W_ih, const float* __restrict__ W_hh,
        const float* __restrict__ c0,   const float* __restrict__ mem0,
        const float* __restrict__ b_kr, const float* __restrict__ w_br,
        const float* __restrict__ b_kw, const float* __restrict__ w_bw,
        const float* __restrict__ b_e,
        float* __restrict__ out) {
    extern __shared__ float sm[];
    float* sh_w    = sm;                                          // [jl][g][576]
    float* sh_x    = sm + SW_FLOATS;                              // [64][580]
    float* sh_mem  = sm + SW_FLOATS + SX_FLOATS;                  // [128][64]
    float* sh_pre  = sm + SW_FLOATS + SX_FLOATS + SM_FLOATS;      // [g][jl][64]
    float* sh_red2 = sm + SW_FLOATS + SX_FLOATS + SM_FLOATS + SPRE_FLOATS; // [128][9]
    float* sb      = sh_x;  // phase B scratch aliases sh_x

    int cta = blockIdx.x;
    int tid = threadIdx.x;
    int b   = tid & 63;
    int jjp = (tid >> 6) & 1;
    int kh  = tid >> 7;

    // one-time: stage 16 gate weight rows [jl][g][k]
    for (int i = tid; i < SW_FLOATS; i += 256) {
        int k = i % 576, q = i / 576;
        int jl = q >> 2, g = q & 3;
        int row = g*CDIM + cta*4 + jl;
        sh_w[i] = (k < CDIM) ? W_hh[(size_t)row*CDIM + k]
                             : W_ih[(size_t)row*(IDIM+MDIM) + IDIM + (k - CDIM)];
    }
    if (cta < BATCH)
        for (int i = tid; i < SM_FLOATS; i += 256) sh_mem[i] = mem0[i];
    float creg0 = c0[cta*4 + jjp*2 + 0];
    float creg1 = c0[cta*4 + jjp*2 + 1];
    __syncthreads();

    unsigned xa_base = cvta_sm(&sh_x[b*SX_STRIDE + kh*288]);
    unsigned wa_base = cvta_sm(&sh_w[jjp*2*4*576 + kh*288]);

    unsigned target = 0;
    for (int t = 0; t < T_STEPS; t++) {
        int hsel = t & 1, hcur = hsel ^ 1;
        const float* hp = g_h[hsel];

        // ---- stage X = [h | r] as [b][k], and pre into sh_pre[g][jl][b] ----
        for (int i = tid; i < 8192; i += 256) {
            int bb = i >> 7, c4 = (i & 127)*4;
            float4 v = __ldcg((const float4*)&hp[bb*CDIM + c4]);
            *(float4*)&sh_x[bb*SX_STRIDE + c4] = v;
        }
        for (int i = tid; i < 1024; i += 256) {
            int bb = i >> 4, m4 = (i & 15)*4;
            float4 v = __ldcg((const float4*)&g_r[bb*MDIM + m4]);
            *(float4*)&sh_x[bb*SX_STRIDE + 512 + m4] = v;
        }
        {
            int pb = tid & 63, pg = tid >> 6;
            float4 v = *(const float4*)&g_pre[((size_t)t*BATCH + pb)*GATES + pg*512 + cta*4];
            sh_pre[pg*256 +  0 + pb] = v.x;
            sh_pre[pg*256 + 64 + pb] = v.y;
            sh_pre[pg*256 + 128 + pb] = v.z;
            sh_pre[pg*256 + 192 + pb] = v.w;
        }
        __syncthreads();

        // ---- gate GEMM: 8 accumulators (2 j x 4 gates), f32x2 over (even,odd) k ----
        ull a0=0,a1=0,a2=0,a3=0,a4=0,a5=0,a6=0,a7=0;
        {
            unsigned xa = xa_base, wa = wa_base;
            #pragma unroll 4
            for (int it = 0; it < 72; it++) {
                ull x01, x23, w01, w23;
                LDS2(x01, x23, xa, 0);
                LDS2(w01, w23, wa, 0);     fma2(a0,x01,w01); fma2(a0,x23,w23);
                LDS2(w01, w23, wa, 2304);  fma2(a1,x01,w01); fma2(a1,x23,w23);
                LDS2(w01, w23, wa, 4608);  fma2(a2,x01,w01); fma2(a2,x23,w23);
                LDS2(w01, w23, wa, 6912);  fma2(a3,x01,w01); fma2(a3,x23,w23);
                LDS2(w01, w23, wa, 9216);  fma2(a4,x01,w01); fma2(a4,x23,w23);
                LDS2(w01, w23, wa, 11520); fma2(a5,x01,w01); fma2(a5,x23,w23);
                LDS2(w01, w23, wa, 13824); fma2(a6,x01,w01); fma2(a6,x23,w23);
                LDS2(w01, w23, wa, 16128); fma2(a7,x01,w01); fma2(a7,x23,w23);
                xa += 16; wa += 16;
            }
        }
        float s[8];
        { float lo, hi;
          upk(a0,lo,hi); s[0]=lo+hi; upk(a1,lo,hi); s[1]=lo+hi;
          upk(a2,lo,hi); s[2]=lo+hi; upk(a3,lo,hi); s[3]=lo+hi;
          upk(a4,lo,hi); s[4]=lo+hi; upk(a5,lo,hi); s[5]=lo+hi;
          upk(a6,lo,hi); s[6]=lo+hi; upk(a7,lo,hi); s[7]=lo+hi; }
        if (tid >= 128) {
            float* rr = &sh_red2[(tid-128)*9];
            #pragma unroll
            for (int q = 0; q < 8; q++) rr[q] = s[q];
        }
        __syncthreads();

        float* out_t = out + (size_t)t*BATCH*(CDIM+MDIM);
        if (tid < 128) {
            const float* rr = &sh_red2[tid*9];
            #pragma unroll
            for (int jx = 0; jx < 2; jx++) {
                int jl = jjp*2 + jx;
                int j  = cta*4 + jl;
                int ja = jx*4;
                float ai = s[ja+0] + rr[ja+0] + sh_pre[0*256 + jl*64 + b];
                float af = s[ja+1] + rr[ja+1] + sh_pre[1*256 + jl*64 + b];
                float ag = s[ja+2] + rr[ja+2] + sh_pre[2*256 + jl*64 + b];
                float ao = s[ja+3] + rr[ja+3] + sh_pre[3*256 + jl*64 + b];
                float iv = sigmoidf_(ai), fv = sigmoidf_(af), ov = sigmoidf_(ao);
                float gv = tanhf(ag);
                float cr = (jx == 0) ? creg0 : creg1;
                cr = fv*cr + iv*gv;
                if (jx == 0) creg0 = cr; else creg1 = cr;
                float hn = ov * tanhf(cr);
                g_h[hcur][b*CDIM + j] = hn;
                out_t[b*576 + j] = hn;
            }
        }

        target += NCTA; grid_bar(target);

        if (cta < BATCH) {
            phase_mem(cta, tid, sh_mem, sb, g_h[hcur],
                      b_kr, w_br, b_kw, w_bw, b_e,
                      g_av + (size_t)t*BATCH*MDIM, g_r, out_t);
        }

        target += NCTA; grid_bar(target);
    }
}

// ---------------- launch ----------------
extern "C" void kernel_launch(void* const* d_in, const int* in_sizes, int n_in,
                              void* d_out, int out_size) {
    const float* embs = (const float*)d_in[0];
    const float* W_ih = (const float*)d_in[1];
    const float* W_hh = (const float*)d_in[2];
    const float* b_ih = (const float*)d_in[3];
    const float* b_hh = (const float*)d_in[4];
    const float* W_kr = (const float*)d_in[5];
    const float* b_kr = (const float*)d_in[6];
    const float* w_br = (const float*)d_in[7];
    const float* W_kw = (const float*)d_in[8];
    const float* b_kw = (const float*)d_in[9];
    const float* w_bw = (const float*)d_in[10];
    const float* W_e  = (const float*)d_in[11];
    const float* b_e  = (const float*)d_in[12];
    const float* W_a  = (const float*)d_in[13];
    const float* b_a  = (const float*)d_in[14];
    const float* h0   = (const float*)d_in[15];
    const float* c0   = (const float*)d_in[16];
    const float* r0   = (const float*)d_in[17];
    const float* mem0 = (const float*)d_in[18];
    float* out = (float*)d_out;

    float *p_pre, *p_av;
    cudaGetSymbolAddress((void**)&p_pre, g_pre);
    cudaGetSymbolAddress((void**)&p_av,  g_av);

    cudaFuncSetAttribute(persist, cudaFuncAttributeMaxDynamicSharedMemorySize, SMEM_TOT_BYTES);

    init_state<<<128, 256>>>(h0, r0);
    transpose_w<<<128, 256>>>(W_kw, W_kr, W_e);
    gemm_pre<<<dim3(GATES/GP_TN, (T_STEPS*BATCH)/GP_TM), 256>>>(embs, W_ih, b_ih, b_hh, p_pre);
    pre_a_kernel<<<(T_STEPS*BATCH)/4, 256>>>(embs, W_a, b_a, p_av);
    persist<<<NCTA, 256, SMEM_TOT_BYTES>>>(W_ih, W_hh, c0, mem0,
                                           b_kr, w_br, b_kw, w_bw, b_e, out);
}

// round 6
// speedup vs baseline: 1.8245x; 1.2452x over previous
#include <cuda_runtime.h>
#include <math.h>

#define T_STEPS 512
#define BATCH   64
#define IDIM    256
#define CDIM    512
#define NSLOT   128
#define MDIM    64
#define GATES   2048
#define EPSV    1e-8f
#define NCTA    128

typedef unsigned long long ull;

// ---------------- device scratch ----------------
__device__ float g_pre[(size_t)T_STEPS*BATCH*GATES];
__device__ float g_av [(size_t)T_STEPS*BATCH*MDIM];
__device__ float g_WT [3][CDIM*MDIM];     // transposed W_kw, W_kr, W_e : [k][m]
__device__ float g_WAT[IDIM*MDIM];        // transposed W_a : [k][m]
__device__ float g_h  [2][BATCH*CDIM];
__device__ float g_r  [BATCH*MDIM];
__device__ unsigned g_bar;

__device__ __forceinline__ float sigmoidf_(float x) { return 1.f/(1.f+expf(-x)); }
__device__ __forceinline__ float softplusf_(float x){ return (x > 20.f) ? x : log1pf(expf(x)); }

// ---- f32x2 helpers ----
__device__ __forceinline__ void upk(ull v, float& lo, float& hi) {
    asm("mov.b64 {%0, %1}, %2;" : "=f"(lo), "=f"(hi) : "l"(v));
}
__device__ __forceinline__ void fma2(ull& acc, ull a, ull b) {
    asm("fma.rn.f32x2 %0, %1, %2, %0;" : "+l"(acc) : "l"(a), "l"(b));
}
__device__ __forceinline__ unsigned cvta_sm(const void* p) {
    return (unsigned)__cvta_generic_to_shared(p);
}
#define LDS2(lo, hi, addr, OFF) \
  asm volatile("ld.shared.v2.u64 {%0,%1}, [%2+" #OFF "];" : "=l"(lo), "=l"(hi) : "r"(addr))

// ---------------- state init ----------------
__global__ void init_state(const float* __restrict__ h0, const float* __restrict__ r0) {
    int stride = gridDim.x * blockDim.x;
    int t0 = blockIdx.x * blockDim.x + threadIdx.x;
    if (t0 == 0) g_bar = 0u;
    for (int i = t0; i < BATCH*CDIM; i += stride)
        g_h[0][i] = h0[i & (CDIM-1)];
    for (int i = t0; i < BATCH*MDIM; i += stride)
        g_r[i] = r0[i & (MDIM-1)];
}

// ---------------- transpose weights ----------------
__global__ void __launch_bounds__(256)
transpose_w(const float* __restrict__ Wkw, const float* __restrict__ Wkr,
            const float* __restrict__ We,  const float* __restrict__ Wa) {
    int idx = blockIdx.x*256 + threadIdx.x;   // 0..32767
    int k = idx >> 6, m = idx & 63;
    g_WT[0][idx] = Wkw[m*CDIM + k];
    g_WT[1][idx] = Wkr[m*CDIM + k];
    g_WT[2][idx] = We [m*CDIM + k];
    if (idx < IDIM*MDIM)
        g_WAT[idx] = Wa[m*IDIM + k];
}

// ---------------- precompute GEMM: g_pre = emb @ W_ih[:, :256]^T + b ----------------
#define GP_TM 128
#define GP_TN 128
#define GP_TK 8
__global__ void __launch_bounds__(256)
gemm_pre(const float* __restrict__ A, const float* __restrict__ W,
         const float* __restrict__ bih, const float* __restrict__ bhh,
         float* __restrict__ C) {
    __shared__ float As[GP_TK][GP_TM+4];
    __shared__ float Bs[GP_TK][GP_TN+4];
    int tid  = threadIdx.x;
    int row0 = blockIdx.y * GP_TM;
    int col0 = blockIdx.x * GP_TN;
    int tx = tid & 15, ty = tid >> 4;

    ull acc2[8][4];
    #pragma unroll
    for (int i = 0; i < 8; i++)
        #pragma unroll
        for (int p = 0; p < 4; p++) acc2[i][p] = 0ull;

    float bv[8];
    #pragma unroll
    for (int j = 0; j < 8; j++) {
        int col = col0 + tx*8 + j;
        bv[j] = bih[col] + bhh[col];
    }

    for (int k0 = 0; k0 < IDIM; k0 += GP_TK) {
        int e  = tid * 4;
        int rr = e >> 3, kk = e & 7;
        float4 va = *(const float4*)&A[(size_t)(row0+rr)*IDIM + k0 + kk];
        As[kk+0][rr] = va.x; As[kk+1][rr] = va.y; As[kk+2][rr] = va.z; As[kk+3][rr] = va.w;
        float4 vb = *(const float4*)&W[(size_t)(col0+rr)*(IDIM+MDIM) + k0 + kk];
        Bs[kk+0][rr] = vb.x; Bs[kk+1][rr] = vb.y; Bs[kk+2][rr] = vb.z; Bs[kk+3][rr] = vb.w;
        __syncthreads();
        #pragma unroll
        for (int kk2 = 0; kk2 < GP_TK; kk2++) {
            float a[8];
            *(float4*)&a[0] = *(const float4*)&As[kk2][ty*8];
            *(float4*)&a[4] = *(const float4*)&As[kk2][ty*8+4];
            ull b2[4];
            const float* bp = &Bs[kk2][tx*8];
            b2[0] = *(const ull*)(bp+0);
            b2[1] = *(const ull*)(bp+2);
            b2[2] = *(const ull*)(bp+4);
            b2[3] = *(const ull*)(bp+6);
            #pragma unroll
            for (int i = 0; i < 8; i++) {
                ull ad; asm("mov.b64 %0, {%1, %1};" : "=l"(ad) : "f"(a[i]));
                #pragma unroll
                for (int p = 0; p < 4; p++) fma2(acc2[i][p], ad, b2[p]);
            }
        }
        __syncthreads();
    }
    #pragma unroll
    for (int i = 0; i < 8; i++) {
        int row = row0 + ty*8 + i;
        float c[8];
        #pragma unroll
        for (int p = 0; p < 4; p++) upk(acc2[i][p], c[2*p], c[2*p+1]);
        #pragma unroll
        for (int j = 0; j < 8; j += 4) {
            float4 v;
            v.x = c[j+0] + bv[j+0]; v.y = c[j+1] + bv[j+1];
            v.z = c[j+2] + bv[j+2]; v.w = c[j+3] + bv[j+3];
            *(float4*)&C[(size_t)row*GATES + col0 + tx*8 + j] = v;
        }
    }
}

// ---------------- precompute: g_av = tanh(emb @ W_a^T + b_a)  (coalesced, WAT) ----------------
__global__ void __launch_bounds__(256)
pre_a_kernel(const float* __restrict__ embs, const float* __restrict__ b_a,
             float* __restrict__ ga) {
    int lane = threadIdx.x & 31, warp = threadIdx.x >> 5;
    int row = blockIdx.x*8 + warp;              // 0..32767
    const float* er = embs + (size_t)row*IDIM;
    float acc0 = b_a[lane], acc1 = b_a[lane+32];
    #pragma unroll 8
    for (int k = 0; k < IDIM; k++) {
        float e = __ldg(&er[k]);
        acc0 = fmaf(e, g_WAT[k*64 + lane],      acc0);
        acc1 = fmaf(e, g_WAT[k*64 + lane + 32], acc1);
    }
    ga[(size_t)row*MDIM + lane]      = tanhf(acc0);
    ga[(size_t)row*MDIM + lane + 32] = tanhf(acc1);
}

// ---------------- software grid barrier ----------------
__device__ __forceinline__ void grid_bar(unsigned target) {
    __syncthreads();
    if (threadIdx.x == 0) {
        __threadfence();
        atomicAdd(&g_bar, 1u);
        while (*(volatile unsigned*)&g_bar < target) { }
    }
    __syncthreads();
}

// ---------------- smem layout ----------------
#define SW_FLOATS   (4*4*576)      // 9216  : [jl][g][576]
#define SX_STRIDE   580
#define SX_FLOATS   (64*SX_STRIDE) // 37120 : x [b][k]
#define SM_FLOATS   (NSLOT*MDIM)   // 8192
#define SPRE_FLOATS (4*4*64)       // 1024  : [g][jl][b]
#define RED2_OFF    8192           // aliased into sh_x (X dead by then; sync-guarded)
#define SMEM_TOT_BYTES ((SW_FLOATS + SX_FLOATS + SM_FLOATS + SPRE_FLOATS) * 4)

// ---------------- phase B: per-batch NTM memory ops ----------------
__device__ void phase_mem(int bb, int tid, float* sh_mem, float* sb,
                          const float* __restrict__ hc,
                          const float* __restrict__ b_kr, const float* __restrict__ w_br,
                          const float* __restrict__ b_kw, const float* __restrict__ w_bw,
                          const float* __restrict__ b_e,
                          const float* __restrict__ av_t,
                          float* __restrict__ r_out, float* __restrict__ out_t) {
    float* sh_co  = sb;            // 512
    float* sh_kw  = sb + 512;
    float* sh_kr  = sb + 576;
    float* sh_e   = sb + 640;
    float* sh_a   = sb + 704;
    float* sh_wt  = sb + 768;
    float* sh_sim = sb + 896;
    float* sh_nrm = sb + 1024;
    float* sh_scal= sb + 1152;     // 8
    float* sh_red = sb + 1216;     // 768
    float* sh_redP= sb + 2048;     // 3072
    int lane = tid & 31, warp = tid >> 5;

    for (int i = tid; i < CDIM; i += 256) sh_co[i] = __ldcg(&hc[bb*CDIM + i]);
    if (tid < MDIM) sh_a[tid] = av_t[bb*MDIM + tid];
    __syncthreads();

    // ---- projections via float4 loads: thread = (kp 16, mq 16) ----
    {
        int kp = tid >> 4, mq = (tid & 15) * 4;
        float4 aw = {0,0,0,0}, ar = {0,0,0,0}, ae = {0,0,0,0};
        const float* WTw = g_WT[0];
        const float* WTr = g_WT[1];
        const float* WTe = g_WT[2];
        int k0 = kp*32;
        #pragma unroll 4
        for (int k = k0; k < k0+32; k++) {
            float c = sh_co[k];
            float4 u = *(const float4*)&WTw[k*64 + mq];
            aw.x = fmaf(c,u.x,aw.x); aw.y = fmaf(c,u.y,aw.y);
            aw.z = fmaf(c,u.z,aw.z); aw.w = fmaf(c,u.w,aw.w);
            float4 v = *(const float4*)&WTr[k*64 + mq];
            ar.x = fmaf(c,v.x,ar.x); ar.y = fmaf(c,v.y,ar.y);
            ar.z = fmaf(c,v.z,ar.z); ar.w = fmaf(c,v.w,ar.w);
            float4 w = *(const float4*)&WTe[k*64 + mq];
            ae.x = fmaf(c,w.x,ae.x); ae.y = fmaf(c,w.y,ae.y);
            ae.z = fmaf(c,w.z,ae.z); ae.w = fmaf(c,w.w,ae.w);
        }
        *(float4*)&sh_redP[0*1024 + kp*64 + mq] = aw;
        *(float4*)&sh_redP[1*1024 + kp*64 + mq] = ar;
        *(float4*)&sh_redP[2*1024 + kp*64 + mq] = ae;
    }
    __syncthreads();
    if (tid < 192) {
        int arr = tid >> 6, m = tid & 63;
        const float* rp = &sh_redP[arr*1024 + m];
        float v = 0.f;
        #pragma unroll
        for (int u = 0; u < 16; u++) v += rp[u*64];
        if (arr == 0)      sh_kw[m] = tanhf(v + b_kw[m]);
        else if (arr == 1) sh_kr[m] = tanhf(v + b_kr[m]);
        else               sh_e[m]  = sigmoidf_(v + b_e[m]);
    }
    if (warp == 6) {
        float acc = 0.f;
        for (int k = lane; k < CDIM; k += 32) acc += sh_co[k]*w_bw[k];
        #pragma unroll
        for (int off = 16; off > 0; off >>= 1) acc += __shfl_down_sync(0xffffffffu, acc, off);
        if (lane == 0) sh_scal[0] = softplusf_(acc);
    }
    if (warp == 7) {
        float acc = 0.f;
        for (int k = lane; k < CDIM; k += 32) acc += sh_co[k]*w_br[k];
        #pragma unroll
        for (int off = 16; off > 0; off >>= 1) acc += __shfl_down_sync(0xffffffffu, acc, off);
        if (lane == 0) sh_scal[1] = softplusf_(acc);
    }
    __syncthreads();

    // ---- WRITE addressing ----
    for (int n = warp; n < NSLOT; n += 8) {
        const float* Mn = &sh_mem[n*MDIM];
        float m1 = Mn[lane], m2 = Mn[lane+32];
        float s = m1*sh_kw[lane] + m2*sh_kw[lane+32];
        float q = m1*m1 + m2*m2;
        #pragma unroll
        for (int off = 16; off > 0; off >>= 1) {
            s += __shfl_down_sync(0xffffffffu, s, off);
            q += __shfl_down_sync(0xffffffffu, q, off);
        }
        if (lane == 0) { sh_sim[n] = s; sh_nrm[n] = sqrtf(q); }
    }
    if (warp == 0) {
        float kv1 = sh_kw[lane], kv2 = sh_kw[lane+32];
        float q = kv1*kv1 + kv2*kv2;
        #pragma unroll
        for (int off = 16; off > 0; off >>= 1) q += __shfl_down_sync(0xffffffffu, q, off);
        if (lane == 0) sh_scal[2] = sqrtf(q);
    }
    __syncthreads();
    if (tid < NSLOT)
        sh_wt[tid] = sh_scal[0] * (sh_sim[tid] / (sh_nrm[tid]*sh_scal[2] + EPSV));
    __syncthreads();
    if (tid < 32) {
        float v0 = sh_wt[lane], v1 = sh_wt[lane+32], v2 = sh_wt[lane+64], v3 = sh_wt[lane+96];
        float mx = fmaxf(fmaxf(v0,v1), fmaxf(v2,v3));
        #pragma unroll
        for (int off = 16; off > 0; off >>= 1) mx = fmaxf(mx, __shfl_xor_sync(0xffffffffu, mx, off));
        float e0 = expf(v0-mx), e1 = expf(v1-mx), e2 = expf(v2-mx), e3 = expf(v3-mx);
        float ss = e0+e1+e2+e3;
        #pragma unroll
        for (int off = 16; off > 0; off >>= 1) ss += __shfl_xor_sync(0xffffffffu, ss, off);
        float inv = 1.f/ss;
        sh_wt[lane] = e0*inv; sh_wt[lane+32] = e1*inv; sh_wt[lane+64] = e2*inv; sh_wt[lane+96] = e3*inv;
    }
    __syncthreads();

    // ---- memory update ----
    for (int i = tid; i < NSLOT*MDIM/4; i += 256) {
        int n = i >> 4, m4 = (i & 15)*4;
        float wn = sh_wt[n];
        float4 mm = *(float4*)&sh_mem[n*MDIM + m4];
        float4 ee = *(const float4*)&sh_e[m4];
        float4 aa = *(const float4*)&sh_a[m4];
        mm.x = mm.x*(1.f - wn*ee.x) + wn*aa.x;
        mm.y = mm.y*(1.f - wn*ee.y) + wn*aa.y;
        mm.z = mm.z*(1.f - wn*ee.z) + wn*aa.z;
        mm.w = mm.w*(1.f - wn*ee.w) + wn*aa.w;
        *(float4*)&sh_mem[n*MDIM + m4] = mm;
    }
    __syncthreads();

    // ---- READ addressing ----
    for (int n = warp; n < NSLOT; n += 8) {
        const float* Mn = &sh_mem[n*MDIM];
        float m1 = Mn[lane], m2 = Mn[lane+32];
        float s = m1*sh_kr[lane] + m2*sh_kr[lane+32];
        float q = m1*m1 + m2*m2;
        #pragma unroll
        for (int off = 16; off > 0; off >>= 1) {
            s += __shfl_down_sync(0xffffffffu, s, off);
            q += __shfl_down_sync(0xffffffffu, q, off);
        }
        if (lane == 0) { sh_sim[n] = s; sh_nrm[n] = sqrtf(q); }
    }
    if (warp == 0) {
        float kv1 = sh_kr[lane], kv2 = sh_kr[lane+32];
        float q = kv1*kv1 + kv2*kv2;
        #pragma unroll
        for (int off = 16; off > 0; off >>= 1) q += __shfl_down_sync(0xffffffffu, q, off);
        if (lane == 0) sh_scal[3] = sqrtf(q);
    }
    __syncthreads();
    if (tid < NSLOT)
        sh_wt[tid] = sh_scal[1] * (sh_sim[tid] / (sh_nrm[tid]*sh_scal[3] + EPSV));
    __syncthreads();
    if (tid < 32) {
        float v0 = sh_wt[lane], v1 = sh_wt[lane+32], v2 = sh_wt[lane+64], v3 = sh_wt[lane+96];
        float mx = fmaxf(fmaxf(v0,v1), fmaxf(v2,v3));
        #pragma unroll
        for (int off = 16; off > 0; off >>= 1) mx = fmaxf(mx, __shfl_xor_sync(0xffffffffu, mx, off));
        float e0 = expf(v0-mx), e1 = expf(v1-mx), e2 = expf(v2-mx), e3 = expf(v3-mx);
        float ss = e0+e1+e2+e3;
        #pragma unroll
        for (int off = 16; off > 0; off >>= 1) ss += __shfl_xor_sync(0xffffffffu, ss, off);
        float inv = 1.f/ss;
        sh_wt[lane] = e0*inv; sh_wt[lane+32] = e1*inv; sh_wt[lane+64] = e2*inv; sh_wt[lane+96] = e3*inv;
    }
    __syncthreads();

    // ---- r = wr @ Mem ----
    {
        int m = tid & 63, p = tid >> 6;
        float acc = 0.f;
        int n0 = p*32;
        #pragma unroll 8
        for (int n = n0; n < n0+32; n++)
            acc += sh_wt[n] * sh_mem[n*MDIM + m];
        sh_red[m*4 + p] = acc;
    }
    __syncthreads();
    if (tid < MDIM) {
        float rv = sh_red[tid*4] + sh_red[tid*4+1] + sh_red[tid*4+2] + sh_red[tid*4+3];
        r_out[bb*MDIM + tid] = rv;
        out_t[bb*576 + 512 + tid] = rv;
    }
    __syncthreads();
}

// ---------------- persistent recurrence kernel ----------------
__global__ void __launch_bounds__(256, 1)
persist(const float* __restrict__ W_ih, const float* __restrict__ W_hh,
        const float* __restrict__ c0,   const float* __restrict__ mem0,
        const float* __restrict__ b_kr, const float* __restrict__ w_br,
        const float* __restrict__ b_kw, const float* __restrict__ w_bw,
        const float* __restrict__ b_e,
        float* __restrict__ out) {
    extern __shared__ float sm[];
    float* sh_w    = sm;                                     // [jl][g][576]
    float* sh_x    = sm + SW_FLOATS;                         // [64][580]
    float* sh_mem  = sm + SW_FLOATS + SX_FLOATS;             // [128][64]
    float* sh_pre  = sm + SW_FLOATS + SX_FLOATS + SM_FLOATS; // [g][jl][64]
    float* red2    = sh_x + RED2_OFF;                        // [192][17] (aliased; sync-guarded)
    float* sb      = sh_x;                                   // phase B scratch

    int cta = blockIdx.x;
    int tid = threadIdx.x;
    int bp  = tid & 31;            // batch pair base
    int jp  = (tid >> 5) & 1;      // j-pair select
    int kh  = tid >> 6;            // 0..3 k-quarter
    int b0  = bp, b1 = bp + 32;
    int j0  = cta*4 + jp*2;

    // stage 16 gate weight rows [jl][g][k]
    for (int i = tid; i < SW_FLOATS; i += 256) {
        int k = i % 576, q = i / 576;
        int jl = q >> 2, g = q & 3;
        int row = g*CDIM + cta*4 + jl;
        sh_w[i] = (k < CDIM) ? W_hh[(size_t)row*CDIM + k]
                             : W_ih[(size_t)row*(IDIM+MDIM) + IDIM + (k - CDIM)];
    }
    if (cta < BATCH)
        for (int i = tid; i < SM_FLOATS; i += 256) sh_mem[i] = mem0[i];
    float c00 = c0[j0], c01 = c0[j0+1];   // b0
    float c10 = c00,    c11 = c01;        // b1 (same init value)
    __syncthreads();

    unsigned xa0_base = cvta_sm(&sh_x[b0*SX_STRIDE + kh*144]);
    unsigned xa1_base = cvta_sm(&sh_x[b1*SX_STRIDE + kh*144]);
    unsigned wa_base  = cvta_sm(sh_w) + (unsigned)(jp*18432 + kh*576);

    unsigned target = 0;
    for (int t = 0; t < T_STEPS; t++) {
        int hsel = t & 1, hcur = hsel ^ 1;
        const float* hp = g_h[hsel];

        // ---- stage X = [h | r] as [b][k]; gather pre ----
        for (int i = tid; i < 8192; i += 256) {
            int bb = i >> 7, c4 = (i & 127)*4;
            float4 v = __ldcg((const float4*)&hp[bb*CDIM + c4]);
            *(float4*)&sh_x[bb*SX_STRIDE + c4] = v;
        }
        for (int i = tid; i < 1024; i += 256) {
            int bb = i >> 4, m4 = (i & 15)*4;
            float4 v = __ldcg((const float4*)&g_r[bb*MDIM + m4]);
            *(float4*)&sh_x[bb*SX_STRIDE + 512 + m4] = v;
        }
        {
            int pb = tid & 63, pg = tid >> 6;
            float4 v = *(const float4*)&g_pre[((size_t)t*BATCH + pb)*GATES + pg*512 + cta*4];
            sh_pre[pg*256 +   0 + pb] = v.x;
            sh_pre[pg*256 +  64 + pb] = v.y;
            sh_pre[pg*256 + 128 + pb] = v.z;
            sh_pre[pg*256 + 192 + pb] = v.w;
        }
        __syncthreads();

        // ---- gate GEMM: 16 acc (2b x 2j x 4g), 36 iters of 4k ----
        ull A0[8], A1[8];
        #pragma unroll
        for (int q = 0; q < 8; q++) { A0[q] = 0ull; A1[q] = 0ull; }
        {
            unsigned xa0 = xa0_base, xa1 = xa1_base, wa = wa_base;
            #pragma unroll 4
            for (int it = 0; it < 36; it++) {
                ull x0a, x0b, x1a, x1b, wA, wB;
                LDS2(x0a, x0b, xa0, 0);
                LDS2(x1a, x1b, xa1, 0);
                LDS2(wA, wB, wa, 0);
                fma2(A0[0],x0a,wA); fma2(A0[0],x0b,wB); fma2(A1[0],x1a,wA); fma2(A1[0],x1b,wB);
                LDS2(wA, wB, wa, 2304);
                fma2(A0[1],x0a,wA); fma2(A0[1],x0b,wB); fma2(A1[1],x1a,wA); fma2(A1[1],x1b,wB);
                LDS2(wA, wB, wa, 4608);
                fma2(A0[2],x0a,wA); fma2(A0[2],x0b,wB); fma2(A1[2],x1a,wA); fma2(A1[2],x1b,wB);
                LDS2(wA, wB, wa, 6912);
                fma2(A0[3],x0a,wA); fma2(A0[3],x0b,wB); fma2(A1[3],x1a,wA); fma2(A1[3],x1b,wB);
                LDS2(wA, wB, wa, 9216);
                fma2(A0[4],x0a,wA); fma2(A0[4],x0b,wB); fma2(A1[4],x1a,wA); fma2(A1[4],x1b,wB);
                LDS2(wA, wB, wa, 11520);
                fma2(A0[5],x0a,wA); fma2(A0[5],x0b,wB); fma2(A1[5],x1a,wA); fma2(A1[5],x1b,wB);
                LDS2(wA, wB, wa, 13824);
                fma2(A0[6],x0a,wA); fma2(A0[6],x0b,wB); fma2(A1[6],x1a,wA); fma2(A1[6],x1b,wB);
                LDS2(wA, wB, wa, 16128);
                fma2(A0[7],x0a,wA); fma2(A0[7],x0b,wB); fma2(A1[7],x1a,wA); fma2(A1[7],x1b,wB);
                xa0 += 16; xa1 += 16; wa += 16;
            }
        }
        float s0[8], s1[8];
        #pragma unroll
        for (int q = 0; q < 8; q++) {
            float lo, hi;
            upk(A0[q], lo, hi); s0[q] = lo + hi;
            upk(A1[q], lo, hi); s1[q] = lo + hi;
        }
        // X is dead from here on, but red2 ALIASES the X region — wait for
        // every warp to finish its GEMM reads before clobbering it.
        __syncthreads();
        if (kh != 0) {
            float* rr = &red2[((kh-1)*64 + jp*32 + bp)*17];
            #pragma unroll
            for (int q = 0; q < 8; q++) { rr[q] = s0[q]; rr[8+q] = s1[q]; }
        }
        __syncthreads();

        float* out_t = out + (size_t)t*BATCH*(CDIM+MDIM);
        if (kh == 0) {
            #pragma unroll
            for (int u = 0; u < 3; u++) {
                const float* rr = &red2[(u*64 + jp*32 + bp)*17];
                #pragma unroll
                for (int q = 0; q < 8; q++) { s0[q] += rr[q]; s1[q] += rr[8+q]; }
            }
            #pragma unroll
            for (int bi = 0; bi < 2; bi++) {
                int b = (bi == 0) ? b0 : b1;
                const float* sv = (bi == 0) ? s0 : s1;
                #pragma unroll
                for (int jx = 0; jx < 2; jx++) {
                    int jl = jp*2 + jx;
                    int j  = cta*4 + jl;
                    float ai = sv[jx*4+0] + sh_pre[0*256 + jl*64 + b];
                    float af = sv[jx*4+1] + sh_pre[1*256 + jl*64 + b];
                    float ag = sv[jx*4+2] + sh_pre[2*256 + jl*64 + b];
                    float ao = sv[jx*4+3] + sh_pre[3*256 + jl*64 + b];
                    float iv = sigmoidf_(ai), fv = sigmoidf_(af), ov = sigmoidf_(ao);
                    float gv = tanhf(ag);
                    float cr;
                    if (bi == 0) cr = (jx == 0) ? c00 : c01;
                    else         cr = (jx == 0) ? c10 : c11;
                    cr = fv*cr + iv*gv;
                    if (bi == 0) { if (jx == 0) c00 = cr; else c01 = cr; }
                    else         { if (jx == 0) c10 = cr; else c11 = cr; }
                    float hn = ov * tanhf(cr);
                    g_h[hcur][b*CDIM + j] = hn;
                    out_t[b*576 + j] = hn;
                }
            }
        }

        target += NCTA; grid_bar(target);

        if (cta < BATCH) {
            phase_mem(cta, tid, sh_mem, sb, g_h[hcur],
                      b_kr, w_br, b_kw, w_bw, b_e,
                      g_av + (size_t)t*BATCH*MDIM, g_r, out_t);
        }

        target += NCTA; grid_bar(target);
    }
}

// ---------------- launch ----------------
extern "C" void kernel_launch(void* const* d_in, const int* in_sizes, int n_in,
                              void* d_out, int out_size) {
    const float* embs = (const float*)d_in[0];
    const float* W_ih = (const float*)d_in[1];
    const float* W_hh = (const float*)d_in[2];
    const float* b_ih = (const float*)d_in[3];
    const float* b_hh = (const float*)d_in[4];
    const float* W_kr = (const float*)d_in[5];
    const float* b_kr = (const float*)d_in[6];
    const float* w_br = (const float*)d_in[7];
    const float* W_kw = (const float*)d_in[8];
    const float* b_kw = (const float*)d_in[9];
    const float* w_bw = (const float*)d_in[10];
    const float* W_e  = (const float*)d_in[11];
    const float* b_e  = (const float*)d_in[12];
    const float* W_a  = (const float*)d_in[13];
    const float* b_a  = (const float*)d_in[14];
    const float* h0   = (const float*)d_in[15];
    const float* c0   = (const float*)d_in[16];
    const float* r0   = (const float*)d_in[17];
    const float* mem0 = (const float*)d_in[18];
    float* out = (float*)d_out;

    float *p_pre, *p_av;
    cudaGetSymbolAddress((void**)&p_pre, g_pre);
    cudaGetSymbolAddress((void**)&p_av,  g_av);

    cudaFuncSetAttribute(persist, cudaFuncAttributeMaxDynamicSharedMemorySize, SMEM_TOT_BYTES);

    init_state<<<128, 256>>>(h0, r0);
    transpose_w<<<128, 256>>>(W_kw, W_kr, W_e, W_a);
    gemm_pre<<<dim3(GATES/GP_TN, (T_STEPS*BATCH)/GP_TM), 256>>>(embs, W_ih, b_ih, b_hh, p_pre);
    pre_a_kernel<<<(T_STEPS*BATCH)/8, 256>>>(embs, b_a, p_av);
    persist<<<NCTA, 256, SMEM_TOT_BYTES>>>(W_ih, W_hh, c0, mem0,
                                           b_kr, w_br, b_kw, w_bw, b_e, out);
}

// round 8
// speedup vs baseline: 2.1621x; 1.1851x over previous
#include <cuda_runtime.h>
#include <math.h>

#define T_STEPS 512
#define BATCH   64
#define IDIM    256
#define CDIM    512
#define NSLOT   128
#define MDIM    64
#define GATES   2048
#define EPSV    1e-8f
#define NCTA    128

typedef unsigned long long ull;

// ---------------- device scratch ----------------
__device__ float g_pre[(size_t)T_STEPS*BATCH*GATES];
__device__ float g_av [(size_t)T_STEPS*BATCH*MDIM];
__device__ float g_WT [3][CDIM*MDIM];     // transposed W_kw, W_kr, W_e : [k][m]
__device__ float g_WAT[IDIM*MDIM];        // transposed W_a : [k][m]
__device__ float g_h  [2][BATCH*CDIM];
__device__ float g_r  [BATCH*MDIM];
__device__ unsigned g_bar;

__device__ __forceinline__ float sigmoidf_(float x) { return 1.f/(1.f+expf(-x)); }
__device__ __forceinline__ float softplusf_(float x){ return (x > 20.f) ? x : log1pf(expf(x)); }

// ---- f32x2 helpers ----
__device__ __forceinline__ ull pk2(float lo, float hi) {
    ull r; asm("mov.b64 %0, {%1, %2};" : "=l"(r) : "f"(lo), "f"(hi)); return r;
}
__device__ __forceinline__ void upk(ull v, float& lo, float& hi) {
    asm("mov.b64 {%0, %1}, %2;" : "=f"(lo), "=f"(hi) : "l"(v));
}
__device__ __forceinline__ void fma2(ull& acc, ull a, ull b) {
    asm("fma.rn.f32x2 %0, %1, %2, %0;" : "+l"(acc) : "l"(a), "l"(b));
}

// ---------------- state init ----------------
__global__ void init_state(const float* __restrict__ h0, const float* __restrict__ r0) {
    int stride = gridDim.x * blockDim.x;
    int t0 = blockIdx.x * blockDim.x + threadIdx.x;
    if (t0 == 0) g_bar = 0u;
    for (int i = t0; i < BATCH*CDIM; i += stride)
        g_h[0][i] = h0[i & (CDIM-1)];
    for (int i = t0; i < BATCH*MDIM; i += stride)
        g_r[i] = r0[i & (MDIM-1)];
}

// ---------------- transpose weights ----------------
__global__ void __launch_bounds__(256)
transpose_w(const float* __restrict__ Wkw, const float* __restrict__ Wkr,
            const float* __restrict__ We,  const float* __restrict__ Wa) {
    int idx = blockIdx.x*256 + threadIdx.x;   // 0..32767
    int k = idx >> 6, m = idx & 63;
    g_WT[0][idx] = Wkw[m*CDIM + k];
    g_WT[1][idx] = Wkr[m*CDIM + k];
    g_WT[2][idx] = We [m*CDIM + k];
    if (idx < IDIM*MDIM)
        g_WAT[idx] = Wa[m*IDIM + k];
}

// ---------------- precompute GEMM: g_pre = emb @ W_ih[:, :256]^T + b ----------------
#define GP_TM 128
#define GP_TN 128
#define GP_TK 8
__global__ void __launch_bounds__(256)
gemm_pre(const float* __restrict__ A, const float* __restrict__ W,
         const float* __restrict__ bih, const float* __restrict__ bhh,
         float* __restrict__ C) {
    __shared__ float As[GP_TK][GP_TM+4];
    __shared__ float Bs[GP_TK][GP_TN+4];
    int tid  = threadIdx.x;
    int row0 = blockIdx.y * GP_TM;
    int col0 = blockIdx.x * GP_TN;
    int tx = tid & 15, ty = tid >> 4;

    ull acc2[8][4];
    #pragma unroll
    for (int i = 0; i < 8; i++)
        #pragma unroll
        for (int p = 0; p < 4; p++) acc2[i][p] = 0ull;

    float bv[8];
    #pragma unroll
    for (int j = 0; j < 8; j++) {
        int col = col0 + tx*8 + j;
        bv[j] = bih[col] + bhh[col];
    }

    for (int k0 = 0; k0 < IDIM; k0 += GP_TK) {
        int e  = tid * 4;
        int rr = e >> 3, kk = e & 7;
        float4 va = *(const float4*)&A[(size_t)(row0+rr)*IDIM + k0 + kk];
        As[kk+0][rr] = va.x; As[kk+1][rr] = va.y; As[kk+2][rr] = va.z; As[kk+3][rr] = va.w;
        float4 vb = *(const float4*)&W[(size_t)(col0+rr)*(IDIM+MDIM) + k0 + kk];
        Bs[kk+0][rr] = vb.x; Bs[kk+1][rr] = vb.y; Bs[kk+2][rr] = vb.z; Bs[kk+3][rr] = vb.w;
        __syncthreads();
        #pragma unroll
        for (int kk2 = 0; kk2 < GP_TK; kk2++) {
            float a[8];
            *(float4*)&a[0] = *(const float4*)&As[kk2][ty*8];
            *(float4*)&a[4] = *(const float4*)&As[kk2][ty*8+4];
            ull b2[4];
            const float* bp = &Bs[kk2][tx*8];
            b2[0] = *(const ull*)(bp+0);
            b2[1] = *(const ull*)(bp+2);
            b2[2] = *(const ull*)(bp+4);
            b2[3] = *(const ull*)(bp+6);
            #pragma unroll
            for (int i = 0; i < 8; i++) {
                ull ad; asm("mov.b64 %0, {%1, %1};" : "=l"(ad) : "f"(a[i]));
                #pragma unroll
                for (int p = 0; p < 4; p++) fma2(acc2[i][p], ad, b2[p]);
            }
        }
        __syncthreads();
    }
    #pragma unroll
    for (int i = 0; i < 8; i++) {
        int row = row0 + ty*8 + i;
        float c[8];
        #pragma unroll
        for (int p = 0; p < 4; p++) upk(acc2[i][p], c[2*p], c[2*p+1]);
        #pragma unroll
        for (int j = 0; j < 8; j += 4) {
            float4 v;
            v.x = c[j+0] + bv[j+0]; v.y = c[j+1] + bv[j+1];
            v.z = c[j+2] + bv[j+2]; v.w = c[j+3] + bv[j+3];
            *(float4*)&C[(size_t)row*GATES + col0 + tx*8 + j] = v;
        }
    }
}

// ---------------- precompute: g_av = tanh(emb @ W_a^T + b_a) ----------------
__global__ void __launch_bounds__(256)
pre_a_kernel(const float* __restrict__ embs, const float* __restrict__ b_a,
             float* __restrict__ ga) {
    int lane = threadIdx.x & 31, warp = threadIdx.x >> 5;
    int row = blockIdx.x*8 + warp;
    const float* er = embs + (size_t)row*IDIM;
    float acc0 = b_a[lane], acc1 = b_a[lane+32];
    #pragma unroll 8
    for (int k = 0; k < IDIM; k++) {
        float e = __ldg(&er[k]);
        acc0 = fmaf(e, g_WAT[k*64 + lane],      acc0);
        acc1 = fmaf(e, g_WAT[k*64 + lane + 32], acc1);
    }
    ga[(size_t)row*MDIM + lane]      = tanhf(acc0);
    ga[(size_t)row*MDIM + lane + 32] = tanhf(acc1);
}

// ---------------- software grid barrier (release/acquire) ----------------
__device__ __forceinline__ void grid_bar(unsigned target) {
    __syncthreads();
    if (threadIdx.x == 0) {
        asm volatile("red.release.gpu.global.add.u32 [%0], 1;" :: "l"(&g_bar) : "memory");
        unsigned v;
        do {
            asm volatile("ld.acquire.gpu.global.u32 %0, [%1];" : "=r"(v) : "l"(&g_bar) : "memory");
        } while (v < target);
    }
    __syncthreads();
}

// ---------------- smem layout ----------------
#define SW_FLOATS   (4*4*576)      // 9216  : [jl*4+g][576]
#define SX_STRIDE   580
#define SX_FLOATS   (64*SX_STRIDE) // 37120
#define SM_STRIDE   65
#define SM_FLOATS   (NSLOT*SM_STRIDE)  // 8320
#define SPRE_FLOATS (4*4*64)       // 1024
#define RED2_OFF    8192           // aliased into sh_x (X dead; sync-guarded)
#define SMEM_TOT_BYTES ((SW_FLOATS + SX_FLOATS + SM_FLOATS + SPRE_FLOATS) * 4)

// ---------------- phase B: per-batch NTM memory ops ----------------
__device__ void phase_mem(int bb, int tid, float* sh_mem, float* sb,
                          const float* __restrict__ hc,
                          const float* __restrict__ b_kr, const float* __restrict__ w_br,
                          const float* __restrict__ b_kw, const float* __restrict__ w_bw,
                          const float* __restrict__ b_e,
                          const float* __restrict__ av_t,
                          float* __restrict__ r_out, float* __restrict__ out_t) {
    float* sh_co  = sb;            // 512
    float* sh_kw  = sb + 512;
    float* sh_kr  = sb + 576;
    float* sh_e   = sb + 640;
    float* sh_a   = sb + 704;
    float* sh_wt  = sb + 768;      // 128
    float* sh_scal= sb + 1152;     // 8
    float* sh_red = sb + 1216;     // 768
    float* sh_redP= sb + 2048;     // 3072
    int lane = tid & 31, warp = tid >> 5;

    for (int i = tid; i < CDIM; i += 256) sh_co[i] = __ldcg(&hc[bb*CDIM + i]);
    if (tid < MDIM) sh_a[tid] = av_t[bb*MDIM + tid];
    __syncthreads();

    // ---- projections via float4 loads: thread = (kp 16, mq 16) ----
    {
        int kp = tid >> 4, mq = (tid & 15) * 4;
        float4 aw = {0,0,0,0}, ar = {0,0,0,0}, ae = {0,0,0,0};
        const float* WTw = g_WT[0];
        const float* WTr = g_WT[1];
        const float* WTe = g_WT[2];
        int k0 = kp*32;
        #pragma unroll 4
        for (int k = k0; k < k0+32; k++) {
            float c = sh_co[k];
            float4 u = *(const float4*)&WTw[k*64 + mq];
            aw.x = fmaf(c,u.x,aw.x); aw.y = fmaf(c,u.y,aw.y);
            aw.z = fmaf(c,u.z,aw.z); aw.w = fmaf(c,u.w,aw.w);
            float4 v = *(const float4*)&WTr[k*64 + mq];
            ar.x = fmaf(c,v.x,ar.x); ar.y = fmaf(c,v.y,ar.y);
            ar.z = fmaf(c,v.z,ar.z); ar.w = fmaf(c,v.w,ar.w);
            float4 w = *(const float4*)&WTe[k*64 + mq];
            ae.x = fmaf(c,w.x,ae.x); ae.y = fmaf(c,w.y,ae.y);
            ae.z = fmaf(c,w.z,ae.z); ae.w = fmaf(c,w.w,ae.w);
        }
        *(float4*)&sh_redP[0*1024 + kp*64 + mq] = aw;
        *(float4*)&sh_redP[1*1024 + kp*64 + mq] = ar;
        *(float4*)&sh_redP[2*1024 + kp*64 + mq] = ae;
    }
    __syncthreads();
    if (tid < 192) {
        int arr = tid >> 6, m = tid & 63;
        const float* rp = &sh_redP[arr*1024 + m];
        float v = 0.f;
        #pragma unroll
        for (int u = 0; u < 16; u++) v += rp[u*64];
        if (arr == 0)      sh_kw[m] = tanhf(v + b_kw[m]);
        else if (arr == 1) sh_kr[m] = tanhf(v + b_kr[m]);
        else               sh_e[m]  = sigmoidf_(v + b_e[m]);
    }
    if (warp == 6) {
        float acc = 0.f;
        for (int k = lane; k < CDIM; k += 32) acc += sh_co[k]*w_bw[k];
        #pragma unroll
        for (int off = 16; off > 0; off >>= 1) acc += __shfl_down_sync(0xffffffffu, acc, off);
        if (lane == 0) sh_scal[0] = softplusf_(acc);
    }
    if (warp == 7) {
        float acc = 0.f;
        for (int k = lane; k < CDIM; k += 32) acc += sh_co[k]*w_br[k];
        #pragma unroll
        for (int off = 16; off > 0; off >>= 1) acc += __shfl_down_sync(0xffffffffu, acc, off);
        if (lane == 0) sh_scal[1] = softplusf_(acc);
    }
    __syncthreads();

    // ================= WRITE addressing: thread = (n 128, half 2) =================
    {
        int n = tid & 127, half = tid >> 7;
        const float* Mn = &sh_mem[n*SM_STRIDE + half*32];
        const float* kv = &sh_kw[half*32];
        float s = 0.f, q = 0.f;
        #pragma unroll
        for (int mm = 0; mm < 32; mm++) {
            float mv = Mn[mm];
            s = fmaf(mv, kv[mm], s);
            q = fmaf(mv, mv, q);
        }
        sh_redP[half*128 + n]       = s;
        sh_redP[256 + half*128 + n] = q;
    }
    __syncthreads();
    if (tid < NSLOT) {
        float s = sh_redP[tid] + sh_redP[128+tid];
        float q = sh_redP[256+tid] + sh_redP[384+tid];
        float kn = 0.f;
        #pragma unroll
        for (int m = 0; m < MDIM; m++) kn = fmaf(sh_kw[m], sh_kw[m], kn);
        float denom = sqrtf(q)*sqrtf(kn) + EPSV;
        sh_wt[tid] = sh_scal[0] * (s / denom);
    }
    __syncthreads();
    if (tid < 32) {   // softmax over 128
        float v0 = sh_wt[lane], v1 = sh_wt[lane+32], v2 = sh_wt[lane+64], v3 = sh_wt[lane+96];
        float mx = fmaxf(fmaxf(v0,v1), fmaxf(v2,v3));
        #pragma unroll
        for (int off = 16; off > 0; off >>= 1) mx = fmaxf(mx, __shfl_xor_sync(0xffffffffu, mx, off));
        float e0 = expf(v0-mx), e1 = expf(v1-mx), e2 = expf(v2-mx), e3 = expf(v3-mx);
        float ss = e0+e1+e2+e3;
        #pragma unroll
        for (int off = 16; off > 0; off >>= 1) ss += __shfl_xor_sync(0xffffffffu, ss, off);
        float inv = 1.f/ss;
        sh_wt[lane] = e0*inv; sh_wt[lane+32] = e1*inv; sh_wt[lane+64] = e2*inv; sh_wt[lane+96] = e3*inv;
    }
    __syncthreads();

    // ================= memory update (SCALAR: sh_mem stride 65 is odd) =================
    for (int i = tid; i < NSLOT*MDIM; i += 256) {
        int n = i >> 6, m = i & 63;
        float wn = sh_wt[n];
        float mv = sh_mem[n*SM_STRIDE + m];
        mv = mv*(1.f - wn*sh_e[m]) + wn*sh_a[m];
        sh_mem[n*SM_STRIDE + m] = mv;
    }
    __syncthreads();

    // ================= READ addressing =================
    {
        int n = tid & 127, half = tid >> 7;
        const float* Mn = &sh_mem[n*SM_STRIDE + half*32];
        const float* kv = &sh_kr[half*32];
        float s = 0.f, q = 0.f;
        #pragma unroll
        for (int mm = 0; mm < 32; mm++) {
            float mv = Mn[mm];
            s = fmaf(mv, kv[mm], s);
            q = fmaf(mv, mv, q);
        }
        sh_redP[half*128 + n]       = s;
        sh_redP[256 + half*128 + n] = q;
    }
    __syncthreads();
    if (tid < NSLOT) {
        float s = sh_redP[tid] + sh_redP[128+tid];
        float q = sh_redP[256+tid] + sh_redP[384+tid];
        float kn = 0.f;
        #pragma unroll
        for (int m = 0; m < MDIM; m++) kn = fmaf(sh_kr[m], sh_kr[m], kn);
        float denom = sqrtf(q)*sqrtf(kn) + EPSV;
        sh_wt[tid] = sh_scal[1] * (s / denom);
    }
    __syncthreads();
    if (tid < 32) {
        float v0 = sh_wt[lane], v1 = sh_wt[lane+32], v2 = sh_wt[lane+64], v3 = sh_wt[lane+96];
        float mx = fmaxf(fmaxf(v0,v1), fmaxf(v2,v3));
        #pragma unroll
        for (int off = 16; off > 0; off >>= 1) mx = fmaxf(mx, __shfl_xor_sync(0xffffffffu, mx, off));
        float e0 = expf(v0-mx), e1 = expf(v1-mx), e2 = expf(v2-mx), e3 = expf(v3-mx);
        float ss = e0+e1+e2+e3;
        #pragma unroll
        for (int off = 16; off > 0; off >>= 1) ss += __shfl_xor_sync(0xffffffffu, ss, off);
        float inv = 1.f/ss;
        sh_wt[lane] = e0*inv; sh_wt[lane+32] = e1*inv; sh_wt[lane+64] = e2*inv; sh_wt[lane+96] = e3*inv;
    }
    __syncthreads();

    // ================= r = wr @ Mem =================
    {
        int m = tid & 63, p = tid >> 6;
        float acc = 0.f;
        int n0 = p*32;
        #pragma unroll 8
        for (int n = n0; n < n0+32; n++)
            acc += sh_wt[n] * sh_mem[n*SM_STRIDE + m];
        sh_red[m*4 + p] = acc;
    }
    __syncthreads();
    if (tid < MDIM) {
        float rv = sh_red[tid*4] + sh_red[tid*4+1] + sh_red[tid*4+2] + sh_red[tid*4+3];
        r_out[bb*MDIM + tid] = rv;
        out_t[bb*576 + 512 + tid] = rv;
    }
    __syncthreads();
}

// ---------------- persistent recurrence kernel ----------------
__global__ void __launch_bounds__(256, 1)
persist(const float* __restrict__ W_ih, const float* __restrict__ W_hh,
        const float* __restrict__ c0,   const float* __restrict__ mem0,
        const float* __restrict__ b_kr, const float* __restrict__ w_br,
        const float* __restrict__ b_kw, const float* __restrict__ w_bw,
        const float* __restrict__ b_e,
        float* __restrict__ out) {
    extern __shared__ float sm[];
    float* sh_w    = sm;                                     // [jl*4+g][576]
    float* sh_x    = sm + SW_FLOATS;                         // [64][580]
    float* sh_mem  = sm + SW_FLOATS + SX_FLOATS;             // [128][65]
    float* sh_pre  = sm + SW_FLOATS + SX_FLOATS + SM_FLOATS; // [g][jl][64]
    float* red2    = sh_x + RED2_OFF;                        // aliased; sync-guarded
    float* sb      = sh_x;                                   // phase B scratch

    int cta = blockIdx.x;
    int tid = threadIdx.x;
    int bp  = tid & 31;
    int jp  = (tid >> 5) & 1;
    int kh  = tid >> 6;            // 0..3
    int b0  = bp, b1 = bp + 32;
    int j0  = cta*4 + jp*2;

    // stage 16 gate weight rows [jl*4+g][k]
    for (int i = tid; i < SW_FLOATS; i += 256) {
        int k = i % 576, q = i / 576;
        int jl = q >> 2, g = q & 3;
        int row = g*CDIM + cta*4 + jl;
        sh_w[i] = (k < CDIM) ? W_hh[(size_t)row*CDIM + k]
                             : W_ih[(size_t)row*(IDIM+MDIM) + IDIM + (k - CDIM)];
    }
    if (cta < BATCH)
        for (int i = tid; i < NSLOT*MDIM; i += 256) {
            int n = i >> 6, m = i & 63;
            sh_mem[n*SM_STRIDE + m] = mem0[i];
        }
    float c00 = c0[j0], c01 = c0[j0+1];
    float c10 = c00,    c11 = c01;
    __syncthreads();

    const float* xp0 = &sh_x[b0*SX_STRIDE + kh*144];
    const float* xp1 = &sh_x[b1*SX_STRIDE + kh*144];
    const float* wp  = &sh_w[jp*4608 + kh*144];

    unsigned target = 0;
    for (int t = 0; t < T_STEPS; t++) {
        int hsel = t & 1, hcur = hsel ^ 1;
        const float* hp = g_h[hsel];

        // ---- stage X = [h | r] as [b][k]; gather pre ----
        for (int i = tid; i < 8192; i += 256) {
            int bb = i >> 7, c4 = (i & 127)*4;
            float4 v = __ldcg((const float4*)&hp[bb*CDIM + c4]);
            *(float4*)&sh_x[bb*SX_STRIDE + c4] = v;
        }
        for (int i = tid; i < 1024; i += 256) {
            int bb = i >> 4, m4 = (i & 15)*4;
            float4 v = __ldcg((const float4*)&g_r[bb*MDIM + m4]);
            *(float4*)&sh_x[bb*SX_STRIDE + 512 + m4] = v;
        }
        {
            int pb = tid & 63, pg = tid >> 6;
            float4 v = *(const float4*)&g_pre[((size_t)t*BATCH + pb)*GATES + pg*512 + cta*4];
            sh_pre[pg*256 +   0 + pb] = v.x;
            sh_pre[pg*256 +  64 + pb] = v.y;
            sh_pre[pg*256 + 128 + pb] = v.z;
            sh_pre[pg*256 + 192 + pb] = v.w;
        }
        __syncthreads();

        // ---- gate GEMM: 16 acc (2b x 2j x 4g), plain C++ loads (ptxas pipelines) ----
        ull A0[8], A1[8];
        #pragma unroll
        for (int q = 0; q < 8; q++) { A0[q] = 0ull; A1[q] = 0ull; }
        #pragma unroll 2
        for (int it = 0; it < 36; it++) {
            int kb = it*4;
            float4 x0 = *(const float4*)(xp0 + kb);
            float4 x1 = *(const float4*)(xp1 + kb);
            ull x0a = pk2(x0.x,x0.y), x0b = pk2(x0.z,x0.w);
            ull x1a = pk2(x1.x,x1.y), x1b = pk2(x1.z,x1.w);
            #pragma unroll
            for (int q = 0; q < 8; q++) {
                float4 w = *(const float4*)(wp + q*576 + kb);
                ull wA = pk2(w.x,w.y), wB = pk2(w.z,w.w);
                fma2(A0[q], x0a, wA); fma2(A0[q], x0b, wB);
                fma2(A1[q], x1a, wA); fma2(A1[q], x1b, wB);
            }
        }
        float s0[8], s1[8];
        #pragma unroll
        for (int q = 0; q < 8; q++) {
            float lo, hi;
            upk(A0[q], lo, hi); s0[q] = lo + hi;
            upk(A1[q], lo, hi); s1[q] = lo + hi;
        }
        // red2 aliases X: wait for all GEMM reads before clobbering
        __syncthreads();
        if (kh != 0) {
            float* rr = &red2[((kh-1)*64 + jp*32 + bp)*17];
            #pragma unroll
            for (int q = 0; q < 8; q++) { rr[q] = s0[q]; rr[8+q] = s1[q]; }
        }
        __syncthreads();

        float* out_t = out + (size_t)t*BATCH*(CDIM+MDIM);
        if (kh == 0) {
            #pragma unroll
            for (int u = 0; u < 3; u++) {
                const float* rr = &red2[(u*64 + jp*32 + bp)*17];
                #pragma unroll
                for (int q = 0; q < 8; q++) { s0[q] += rr[q]; s1[q] += rr[8+q]; }
            }
            #pragma unroll
            for (int bi = 0; bi < 2; bi++) {
                int b = (bi == 0) ? b0 : b1;
                const float* sv = (bi == 0) ? s0 : s1;
                #pragma unroll
                for (int jx = 0; jx < 2; jx++) {
                    int jl = jp*2 + jx;
                    int j  = cta*4 + jl;
                    float ai = sv[jx*4+0] + sh_pre[0*256 + jl*64 + b];
                    float af = sv[jx*4+1] + sh_pre[1*256 + jl*64 + b];
                    float ag = sv[jx*4+2] + sh_pre[2*256 + jl*64 + b];
                    float ao = sv[jx*4+3] + sh_pre[3*256 + jl*64 + b];
                    float iv = sigmoidf_(ai), fv = sigmoidf_(af), ov = sigmoidf_(ao);
                    float gv = tanhf(ag);
                    float cr;
                    if (bi == 0) cr = (jx == 0) ? c00 : c01;
                    else         cr = (jx == 0) ? c10 : c11;
                    cr = fv*cr + iv*gv;
                    if (bi == 0) { if (jx == 0) c00 = cr; else c01 = cr; }
                    else         { if (jx == 0) c10 = cr; else c11 = cr; }
                    float hn = ov * tanhf(cr);
                    g_h[hcur][b*CDIM + j] = hn;
                    out_t[b*576 + j] = hn;
                }
            }
        }

        target += NCTA; grid_bar(target);

        if (cta < BATCH) {
            phase_mem(cta, tid, sh_mem, sb, g_h[hcur],
                      b_kr, w_br, b_kw, w_bw, b_e,
                      g_av + (size_t)t*BATCH*MDIM, g_r, out_t);
        }

        target += NCTA; grid_bar(target);
    }
}

// ---------------- launch ----------------
extern "C" void kernel_launch(void* const* d_in, const int* in_sizes, int n_in,
                              void* d_out, int out_size) {
    const float* embs = (const float*)d_in[0];
    const float* W_ih = (const float*)d_in[1];
    const float* W_hh = (const float*)d_in[2];
    const float* b_ih = (const float*)d_in[3];
    const float* b_hh = (const float*)d_in[4];
    const float* W_kr = (const float*)d_in[5];
    const float* b_kr = (const float*)d_in[6];
    const float* w_br = (const float*)d_in[7];
    const float* W_kw = (const float*)d_in[8];
    const float* b_kw = (const float*)d_in[9];
    const float* w_bw = (const float*)d_in[10];
    const float* W_e  = (const float*)d_in[11];
    const float* b_e  = (const float*)d_in[12];
    const float* W_a  = (const float*)d_in[13];
    const float* b_a  = (const float*)d_in[14];
    const float* h0   = (const float*)d_in[15];
    const float* c0   = (const float*)d_in[16];
    const float* r0   = (const float*)d_in[17];
    const float* mem0 = (const float*)d_in[18];
    float* out = (float*)d_out;

    float *p_pre, *p_av;
    cudaGetSymbolAddress((void**)&p_pre, g_pre);
    cudaGetSymbolAddress((void**)&p_av,  g_av);

    cudaFuncSetAttribute(persist, cudaFuncAttributeMaxDynamicSharedMemorySize, SMEM_TOT_BYTES);

    init_state<<<128, 256>>>(h0, r0);
    transpose_w<<<128, 256>>>(W_kw, W_kr, W_e, W_a);
    gemm_pre<<<dim3(GATES/GP_TN, (T_STEPS*BATCH)/GP_TM), 256>>>(embs, W_ih, b_ih, b_hh, p_pre);
    pre_a_kernel<<<(T_STEPS*BATCH)/8, 256>>>(embs, b_a, p_av);
    persist<<<NCTA, 256, SMEM_TOT_BYTES>>>(W_ih, W_hh, c0, mem0,
                                           b_kr, w_br, b_kw, w_bw, b_e, out);
}